// round 10
// baseline (speedup 1.0000x reference)
#include <cuda_runtime.h>
#include <cstdint>
#include <math.h>

// ---------------- problem constants ----------------
#define N_RAYS_C   4096
#define PPR_C      64
#define VD_C       12
#define GRID_C     128
#define ACT_SHIFT_C (-4.5951199f)   // log(1/(1-0.01) - 1)

// activation buffer pitches (multiple of 4 for float4 k-loads)
#define AP 212
#define BP 132
#define KT 16
#define NTHREADS 256

// shared memory layout (floats):
// A 64*212 + B 64*132 + WS 2*16*128 + PD 192 + ALP 64 + WGT 64 + RGB 192
// + VE 24 + ALAST 8 + TI 192 + TFR 192
#define SMEM_FLOATS (64*AP + 64*BP + 2*KT*128 + 192 + 64 + 64 + 192 + 24 + 8 + 192 + 192)
#define SMEM_BYTES  (SMEM_FLOATS * 4)

// ---------------- device scratch (static: no allocation) ----------------
__device__ float g_pool2[VD_C * 64 * 64 * 64];
__device__ float g_pool4[VD_C * 32 * 32 * 32];
__device__ float g_tf[64];   // 60 used

// ---------------- f32x2 helpers ----------------
__device__ __forceinline__ void ffma2(unsigned long long& d, unsigned long long a,
                                      unsigned long long b) {
    asm("fma.rn.f32x2 %0, %1, %2, %0;" : "+l"(d) : "l"(a), "l"(b));
}
__device__ __forceinline__ unsigned long long dup2(float x) {
    unsigned long long r;
    asm("mov.b64 %0, {%1, %1};" : "=l"(r) : "f"(x));
    return r;
}

// ---------------- pooling kernels ----------------
__global__ void pool2_kernel(const float* __restrict__ g) {
    int idx = blockIdx.x * blockDim.x + threadIdx.x;
    const int total = VD_C * 64 * 64 * 64;
    if (idx >= total) return;
    int z = idx & 63, y = (idx >> 6) & 63, x = (idx >> 12) & 63, c = idx >> 18;
    const float* b = g + ((((size_t)c * 128 + 2 * x) * 128 + 2 * y) * 128 + 2 * z);
    float2 a0 = *(const float2*)(b);
    float2 a1 = *(const float2*)(b + 128);
    float2 a2 = *(const float2*)(b + 16384);
    float2 a3 = *(const float2*)(b + 16384 + 128);
    g_pool2[idx] = (a0.x + a0.y + a1.x + a1.y + a2.x + a2.y + a3.x + a3.y) * 0.125f;
}

__global__ void pool4_kernel() {
    int idx = blockIdx.x * blockDim.x + threadIdx.x;
    const int total = VD_C * 32 * 32 * 32;
    if (idx >= total) return;
    int z = idx & 31, y = (idx >> 5) & 31, x = (idx >> 10) & 31, c = idx >> 15;
    const float* b = g_pool2 + ((((size_t)c * 64 + 2 * x) * 64 + 2 * y) * 64 + 2 * z);
    float2 a0 = *(const float2*)(b);
    float2 a1 = *(const float2*)(b + 64);
    float2 a2 = *(const float2*)(b + 4096);
    float2 a3 = *(const float2*)(b + 4096 + 64);
    g_pool4[idx] = (a0.x + a0.y + a1.x + a1.y + a2.x + a2.y + a3.x + a3.y) * 0.125f;
}

// ---------------- timenet (tiny, runs once) ----------------
__global__ void timenet_kernel(const float* __restrict__ ft,
                               const float* __restrict__ w0, const float* __restrict__ b0,
                               const float* __restrict__ w1, const float* __restrict__ b1) {
    __shared__ float temb[9];
    __shared__ float h[128];
    int tid = threadIdx.x;
    if (tid == 0) {
        float t = ft[0];
        temb[0] = t;
        #pragma unroll
        for (int k = 0; k < 4; ++k) {
            temb[1 + k] = sinf(t * (float)(1 << k));
            temb[5 + k] = cosf(t * (float)(1 << k));
        }
    }
    __syncthreads();
    {
        float v = b0[tid];
        #pragma unroll
        for (int k = 0; k < 9; ++k) v = fmaf(temb[k], w0[k * 128 + tid], v);
        h[tid] = fmaxf(v, 0.f);
    }
    __syncthreads();
    if (tid < 60) {
        float v = b1[tid];
        for (int k = 0; k < 128; ++k) v = fmaf(h[k], w1[k * 60 + tid], v);
        g_tf[tid] = v;
    }
}

// ---------------- trilerp helpers ----------------
__device__ __forceinline__ void tri_setup(const float* pd, int D, int* ii, float* ff) {
    float dim = (float)(D - 1);
    float hi = dim - 1e-4f;
    #pragma unroll
    for (int c = 0; c < 3; ++c) {
        float t = (pd[c] + 1.f) * 0.5f * dim;
        t = fminf(fmaxf(t, 0.f), hi);
        float fl = floorf(t);
        ii[c] = (int)fl;
        ff[c] = t - fl;
    }
}

__device__ __forceinline__ float tri_gather(const float* __restrict__ g, int D,
                                            int ix, int iy, int iz,
                                            float fx, float fy, float fz) {
    size_t sx = (size_t)D * D;
    int sy = D;
    const float* b = g + (size_t)ix * sx + (size_t)iy * sy + iz;
    float v000 = __ldg(b),            v001 = __ldg(b + 1);
    float v010 = __ldg(b + sy),       v011 = __ldg(b + sy + 1);
    float v100 = __ldg(b + sx),       v101 = __ldg(b + sx + 1);
    float v110 = __ldg(b + sx + sy),  v111 = __ldg(b + sx + sy + 1);
    float c00 = v000 + (v001 - v000) * fz;
    float c01 = v010 + (v011 - v010) * fz;
    float c10 = v100 + (v101 - v100) * fz;
    float c11 = v110 + (v111 - v110) * fz;
    float c0 = c00 + (c01 - c00) * fy;
    float c1 = c10 + (c11 - c10) * fy;
    return c0 + (c1 - c0) * fx;
}

// ---------------- register-tiled f32x2 GEMM layer ----------------
// 64 points x OUT cols; 256 threads: ci = tid&15 (CP cols), pi = tid>>4 (4 points)
// Weight tiles double-buffered in smem via cp.async.
// INP = padded K (multiple of 16, x cols [INA,INP) must be zero in xs)
// INA = actual K (weight rows >= INA are zero-filled on load)
template <int OUT, int ACT>
__device__ __forceinline__ void mlp_layer(
    const float* __restrict__ W, const float* __restrict__ bias,
    const float* __restrict__ xs, int xp, int INA, int INP,
    float* __restrict__ ys, int yp,
    float* __restrict__ ws, int tid) {
    constexpr int CP = OUT / 16;   // 8 or 4 columns per thread
    constexpr int NP = CP / 2;     // f32x2 pairs per row
    const int ci = tid & 15;
    const int pi = tid >> 4;
    unsigned long long acc[4][NP];
    #pragma unroll
    for (int r = 0; r < 4; ++r)
        #pragma unroll
        for (int j = 0; j < NP; ++j) acc[r][j] = 0ull;

    const int ntiles = INP / KT;
    constexpr int CHUNKS = (KT * OUT) / 4;   // 16B chunks per tile

    // tile loader: cp.async with zero-fill for rows >= INA
    auto load_tile = [&](int t, int buf) {
        const float* src_base = W + (size_t)t * KT * OUT;
        float* dst_base = ws + buf * (KT * 128);
        int rem_floats = (INA - t * KT) * OUT;   // >0 for valid tiles
        #pragma unroll
        for (int c16 = tid; c16 < CHUNKS; c16 += NTHREADS) {
            const float* src = src_base + c16 * 4;
            int sz = ((c16 * 4) < rem_floats) ? 16 : 0;
            if (sz == 0) src = W;  // keep address valid
            unsigned dst = (unsigned)__cvta_generic_to_shared(dst_base + c16 * 4);
            asm volatile("cp.async.ca.shared.global [%0], [%1], 16, %2;"
                         :: "r"(dst), "l"(src), "r"(sz));
        }
        asm volatile("cp.async.commit_group;");
    };

    load_tile(0, 0);
    asm volatile("cp.async.wait_group 0;");
    __syncthreads();

    for (int t = 0; t < ntiles; ++t) {
        const int buf = t & 1;
        if (t + 1 < ntiles) load_tile(t + 1, buf ^ 1);
        const float* xb = xs + (size_t)(pi * 4) * xp + t * KT;
        const float* wb = ws + buf * (KT * 128);
        #pragma unroll
        for (int k4 = 0; k4 < KT; k4 += 4) {
            float4 xv[4];
            #pragma unroll
            for (int r = 0; r < 4; ++r)
                xv[r] = *reinterpret_cast<const float4*>(xb + r * xp + k4);
            #pragma unroll
            for (int kk = 0; kk < 4; ++kk) {
                unsigned long long xx[4];
                #pragma unroll
                for (int r = 0; r < 4; ++r) {
                    float xsv = (kk == 0) ? xv[r].x : (kk == 1) ? xv[r].y
                              : (kk == 2) ? xv[r].z : xv[r].w;
                    xx[r] = dup2(xsv);
                }
                const ulonglong2* wr = reinterpret_cast<const ulonglong2*>(
                    wb + (k4 + kk) * OUT + ci * CP);
                #pragma unroll
                for (int q = 0; q < NP / 2; ++q) {
                    ulonglong2 w2 = wr[q];
                    #pragma unroll
                    for (int r = 0; r < 4; ++r) {
                        ffma2(acc[r][2 * q],     xx[r], w2.x);
                        ffma2(acc[r][2 * q + 1], xx[r], w2.y);
                    }
                }
            }
        }
        asm volatile("cp.async.wait_group 0;");
        __syncthreads();
    }

    #pragma unroll
    for (int j = 0; j < NP; ++j) {
        float b0 = __ldg(bias + ci * CP + 2 * j);
        float b1 = __ldg(bias + ci * CP + 2 * j + 1);
        #pragma unroll
        for (int r = 0; r < 4; ++r) {
            float2 p = *reinterpret_cast<float2*>(&acc[r][j]);
            float v0 = p.x + b0, v1 = p.y + b1;
            if (ACT) { v0 = fmaxf(v0, 0.f); v1 = fmaxf(v1, 0.f); }
            const int row = pi * 4 + r;
            ys[(size_t)row * yp + ci * CP + 2 * j]     = v0;
            ys[(size_t)row * yp + ci * CP + 2 * j + 1] = v1;
        }
    }
}

// ---------------- fused main kernel: one block = one ray ----------------
__global__ void __launch_bounds__(NTHREADS, 2)
voxelmlp_main(const float* __restrict__ ray_pts,
              const float* __restrict__ viewdirs,
              const float* __restrict__ feature,
              const float* __restrict__ density,
              const float* __restrict__ dt_w0, const float* __restrict__ dt_b0,
              const float* __restrict__ dt_w1, const float* __restrict__ dt_b1,
              const float* __restrict__ dt_wo, const float* __restrict__ dt_bo,
              const float* __restrict__ fn_w0, const float* __restrict__ fn_b0,
              const float* __restrict__ dec_wf, const float* __restrict__ dec_bf,
              const float* __restrict__ dec_w0, const float* __restrict__ dec_b0,
              const float* __restrict__ dec_w1, const float* __restrict__ dec_b1,
              float* __restrict__ out) {
    extern __shared__ float sm[];
    float* A     = sm;                    // [64][212]
    float* Bb    = A + 64 * AP;           // [64][132]
    float* WS    = Bb + 64 * BP;          // [2][16][128]
    float* PD    = WS + 2 * KT * 128;     // [64][3]
    float* ALP   = PD + 192;              // [64]
    float* WGT   = ALP + 64;              // [64]
    float* RGB   = WGT + 64;              // [64][3]
    float* VE    = RGB + 192;             // [24]
    float* ALAST = VE + 24;               // [8]
    int*   TI    = reinterpret_cast<int*>(ALAST + 8);   // [64][3]
    float* TFR   = reinterpret_cast<float*>(TI + 192);  // [64][3]

    const int tid   = threadIdx.x;
    const int ray   = blockIdx.x;
    const int gbase = ray * PPR_C;

    // ---- phase 0: deform-net input X = [pts_emb(27), tf(60)], pad -> 96 ----
    if (tid < 64) {
        const int p = tid;
        float* row = A + p * AP;
        #pragma unroll
        for (int d = 0; d < 3; ++d) {
            float v = ray_pts[(size_t)(gbase + p) * 3 + d];
            row[d] = v;
            #pragma unroll
            for (int k = 0; k < 4; ++k) {
                float s, c;
                __sincosf(v * (float)(1 << k), &s, &c);
                row[3 + d * 4 + k]  = s;
                row[15 + d * 4 + k] = c;
            }
        }
    }
    if (tid >= 64 && tid < 67) {  // view embedding, once per ray
        const int d = tid - 64;
        float v = viewdirs[(size_t)ray * 3 + d];
        VE[d] = v;
        #pragma unroll
        for (int k = 0; k < 3; ++k) {
            float s, c;
            __sincosf(v * (float)(1 << k), &s, &c);
            VE[3 + d * 3 + k]  = s;
            VE[12 + d * 3 + k] = c;
        }
    }
    for (int i = tid; i < 64 * 60; i += NTHREADS) {
        int p = i & 63, j = i >> 6;
        A[p * AP + 27 + j] = g_tf[j];
    }
    for (int i = tid; i < 64 * 9; i += NTHREADS) {
        int p = i & 63, j = i >> 6;
        A[p * AP + 87 + j] = 0.f;
    }
    __syncthreads();

    // ---- deformation net ----
    mlp_layer<128, 1>(dt_w0, dt_b0, A, AP, 87, 96, Bb, BP, WS, tid);
    __syncthreads();
    mlp_layer<128, 1>(dt_w1, dt_b1, Bb, BP, 128, 128, A, AP, WS, tid);
    __syncthreads();

    {   // dx = H @ dt_wo + dt_bo ; pts_d = ray_pts + dx  (quad-parallel dot)
        const int p  = tid >> 2;
        const int l4 = tid & 3;
        float d0 = 0.f, d1 = 0.f, d2 = 0.f;
        const float* row = A + p * AP;
        #pragma unroll 8
        for (int k = l4; k < 128; k += 4) {
            float h = row[k];
            d0 = fmaf(h, __ldg(dt_wo + k * 3 + 0), d0);
            d1 = fmaf(h, __ldg(dt_wo + k * 3 + 1), d1);
            d2 = fmaf(h, __ldg(dt_wo + k * 3 + 2), d2);
        }
        d0 += __shfl_xor_sync(0xffffffffu, d0, 1);
        d0 += __shfl_xor_sync(0xffffffffu, d0, 2);
        d1 += __shfl_xor_sync(0xffffffffu, d1, 1);
        d1 += __shfl_xor_sync(0xffffffffu, d1, 2);
        d2 += __shfl_xor_sync(0xffffffffu, d2, 1);
        d2 += __shfl_xor_sync(0xffffffffu, d2, 2);
        if (l4 == 0) {
            PD[p * 3 + 0] = ray_pts[(size_t)(gbase + p) * 3 + 0] + d0 + __ldg(dt_bo + 0);
            PD[p * 3 + 1] = ray_pts[(size_t)(gbase + p) * 3 + 1] + d1 + __ldg(dt_bo + 1);
            PD[p * 3 + 2] = ray_pts[(size_t)(gbase + p) * 3 + 2] + d2 + __ldg(dt_bo + 2);
        }
    }
    __syncthreads();

    // ---- density -> alpha ----
    if (tid < 64) {
        const int p = tid;
        int ii[3]; float ff[3];
        tri_setup(PD + p * 3, GRID_C, ii, ff);
        float dens = tri_gather(density, GRID_C, ii[0], ii[1], ii[2], ff[0], ff[1], ff[2]);
        float x = dens + ACT_SHIFT_C;
        float sp = (x > 20.f) ? x : log1pf(__expf(x));
        ALP[p] = 1.f - __expf(-sp * 0.5f);
    }
    __syncthreads();
    if (tid == 0) {  // per-ray exclusive cumprod
        float T = 1.f;
        for (int i = 0; i < PPR_C; ++i) {
            float a = ALP[i];
            WGT[i] = a * T;
            T *= (1.f - a);
        }
        ALAST[0] = T;
    }

    // ---- 3-scale feature trilerp into X2 cols [0,36) ----
    #pragma unroll 1
    for (int s = 0; s < 3; ++s) {
        const int D = GRID_C >> s;
        if (tid < 64) {
            int ii[3]; float ff[3];
            tri_setup(PD + tid * 3, D, ii, ff);
            TI[tid * 3 + 0] = ii[0]; TI[tid * 3 + 1] = ii[1]; TI[tid * 3 + 2] = ii[2];
            TFR[tid * 3 + 0] = ff[0]; TFR[tid * 3 + 1] = ff[1]; TFR[tid * 3 + 2] = ff[2];
        }
        __syncthreads();
        const float* gp = (s == 0) ? feature : ((s == 1) ? (const float*)g_pool2
                                                         : (const float*)g_pool4);
        const size_t csz = (size_t)D * D * D;
        for (int i = tid; i < 64 * VD_C; i += NTHREADS) {
            int p = i & 63, c = i >> 6;
            float v = tri_gather(gp + (size_t)c * csz, D,
                                 TI[p * 3 + 0], TI[p * 3 + 1], TI[p * 3 + 2],
                                 TFR[p * 3 + 0], TFR[p * 3 + 1], TFR[p * 3 + 2]);
            A[p * AP + s * 12 + c] = v;
        }
        __syncthreads();
    }

    // ---- featurenet input X2 = [sin_emb(feat,2)(180), sin_emb(pts_d,4)(27)] ----
    for (int i = tid; i < 64 * 36; i += NTHREADS) {
        int p = i & 63, d = i >> 6;
        float* row = A + p * AP;
        float f = row[d];
        float s1, c1, s2, c2;
        __sincosf(f, &s1, &c1);
        __sincosf(2.f * f, &s2, &c2);
        row[36 + 2 * d]  = s1;  row[37 + 2 * d]  = s2;
        row[108 + 2 * d] = c1;  row[109 + 2 * d] = c2;
    }
    if (tid < 64) {
        const int p = tid;
        float* row = A + p * AP;
        #pragma unroll
        for (int d = 0; d < 3; ++d) {
            float v = PD[p * 3 + d];
            row[180 + d] = v;
            #pragma unroll
            for (int k = 0; k < 4; ++k) {
                float s, c;
                __sincosf(v * (float)(1 << k), &s, &c);
                row[183 + d * 4 + k] = s;
                row[195 + d * 4 + k] = c;
            }
        }
        row[207] = 0.f;
    }
    __syncthreads();

    // ---- featurenet + decoder ----
    mlp_layer<128, 1>(fn_w0, fn_b0, A, AP, 207, 208, Bb, BP, WS, tid);
    __syncthreads();
    mlp_layer<128, 0>(dec_wf, dec_bf, Bb, BP, 128, 128, A, AP, WS, tid);
    __syncthreads();
    if (tid < 64) {  // append vemb; pad to 160
        float* row = A + tid * AP;
        #pragma unroll
        for (int j = 0; j < 21; ++j) row[128 + j] = VE[j];
        #pragma unroll
        for (int j = 149; j < 160; ++j) row[j] = 0.f;
    }
    __syncthreads();
    mlp_layer<64, 1>(dec_w0, dec_b0, A, AP, 149, 160, Bb, BP, WS, tid);
    __syncthreads();

    {   // final 64->3 + sigmoid (quad-parallel)
        const int p  = tid >> 2;
        const int l4 = tid & 3;
        float r0 = 0.f, r1 = 0.f, r2 = 0.f;
        const float* row = Bb + p * BP;
        #pragma unroll 4
        for (int k = l4; k < 64; k += 4) {
            float h = row[k];
            r0 = fmaf(h, __ldg(dec_w1 + k * 3 + 0), r0);
            r1 = fmaf(h, __ldg(dec_w1 + k * 3 + 1), r1);
            r2 = fmaf(h, __ldg(dec_w1 + k * 3 + 2), r2);
        }
        r0 += __shfl_xor_sync(0xffffffffu, r0, 1);
        r0 += __shfl_xor_sync(0xffffffffu, r0, 2);
        r1 += __shfl_xor_sync(0xffffffffu, r1, 1);
        r1 += __shfl_xor_sync(0xffffffffu, r1, 2);
        r2 += __shfl_xor_sync(0xffffffffu, r2, 1);
        r2 += __shfl_xor_sync(0xffffffffu, r2, 2);
        if (l4 == 0) {
            r0 += __ldg(dec_b1 + 0);
            r1 += __ldg(dec_b1 + 1);
            r2 += __ldg(dec_b1 + 2);
            RGB[p * 3 + 0] = 1.f / (1.f + __expf(-r0));
            RGB[p * 3 + 1] = 1.f / (1.f + __expf(-r1));
            RGB[p * 3 + 2] = 1.f / (1.f + __expf(-r2));
        }
    }
    __syncthreads();

    if (tid < 3) {  // composite with white background
        float s = ALAST[0];
        for (int p = 0; p < PPR_C; ++p) s = fmaf(WGT[p], RGB[p * 3 + tid], s);
        out[(size_t)ray * 3 + tid] = s;
    }
}

// ---------------- launch ----------------
extern "C" void kernel_launch(void* const* d_in, const int* in_sizes, int n_in,
                              void* d_out, int out_size) {
    (void)in_sizes; (void)n_in; (void)out_size;
    const float* ray_pts    = (const float*)d_in[0];
    const float* viewdirs   = (const float*)d_in[1];
    const float* frame_time = (const float*)d_in[2];
    const float* feature    = (const float*)d_in[3];
    const float* density    = (const float*)d_in[4];
    const float* tn_w0 = (const float*)d_in[5];
    const float* tn_b0 = (const float*)d_in[6];
    const float* tn_w1 = (const float*)d_in[7];
    const float* tn_b1 = (const float*)d_in[8];
    const float* dt_w0 = (const float*)d_in[9];
    const float* dt_b0 = (const float*)d_in[10];
    const float* dt_w1 = (const float*)d_in[11];
    const float* dt_b1 = (const float*)d_in[12];
    const float* dt_wo = (const float*)d_in[13];
    const float* dt_bo = (const float*)d_in[14];
    const float* fn_w0 = (const float*)d_in[15];
    const float* fn_b0 = (const float*)d_in[16];
    const float* dec_wf = (const float*)d_in[17];
    const float* dec_bf = (const float*)d_in[18];
    const float* dec_w0 = (const float*)d_in[19];
    const float* dec_b0 = (const float*)d_in[20];
    const float* dec_w1 = (const float*)d_in[21];
    const float* dec_b1 = (const float*)d_in[22];
    float* out = (float*)d_out;

    cudaFuncSetAttribute(voxelmlp_main, cudaFuncAttributeMaxDynamicSharedMemorySize,
                         SMEM_BYTES);

    {
        const int total = VD_C * 64 * 64 * 64;
        pool2_kernel<<<(total + 255) / 256, 256>>>(feature);
    }
    {
        const int total = VD_C * 32 * 32 * 32;
        pool4_kernel<<<(total + 255) / 256, 256>>>();
    }
    timenet_kernel<<<1, 128>>>(frame_time, tn_w0, tn_b0, tn_w1, tn_b1);

    voxelmlp_main<<<N_RAYS_C, NTHREADS, SMEM_BYTES>>>(
        ray_pts, viewdirs, feature, density,
        dt_w0, dt_b0, dt_w1, dt_b1, dt_wo, dt_bo,
        fn_w0, fn_b0, dec_wf, dec_bf,
        dec_w0, dec_b0, dec_w1, dec_b1,
        out);
}

// round 11
// speedup vs baseline: 1.0494x; 1.0494x over previous
#include <cuda_runtime.h>
#include <cstdint>
#include <math.h>

// ---------------- problem constants ----------------
#define N_RAYS_C   4096
#define PPR_C      64
#define VD_C       12
#define GRID_C     128
#define ACT_SHIFT_C (-4.5951199f)   // log(1/(1-0.01) - 1)

// activation buffer pitches (multiple of 4 for float4 k-loads)
#define AP 212
#define BP 132
#define KT 16
#define NTHREADS 256

// shared memory layout (floats):
// A 64*212 + B 64*132 + WS 2*16*128 + PD 192 + ALP 64 + WGT 64 + RGB 192
// + VE 24 + ALAST 8 + TI 192 + TFR 192
#define SMEM_FLOATS (64*AP + 64*BP + 2*KT*128 + 192 + 64 + 64 + 192 + 24 + 8 + 192 + 192)
#define SMEM_BYTES  (SMEM_FLOATS * 4)

// ---------------- device scratch (static: no allocation) ----------------
__device__ float g_pool2[VD_C * 64 * 64 * 64];
__device__ float g_pool4[VD_C * 32 * 32 * 32];
__device__ float g_tf[64];   // 60 used

// ---------------- f32x2 helpers ----------------
__device__ __forceinline__ void ffma2(unsigned long long& d, unsigned long long a,
                                      unsigned long long b) {
    asm("fma.rn.f32x2 %0, %1, %2, %0;" : "+l"(d) : "l"(a), "l"(b));
}
__device__ __forceinline__ unsigned long long dup2(float x) {
    unsigned long long r;
    asm("mov.b64 %0, {%1, %1};" : "=l"(r) : "f"(x));
    return r;
}

// ---------------- pooling kernels ----------------
__global__ void pool2_kernel(const float* __restrict__ g) {
    int idx = blockIdx.x * blockDim.x + threadIdx.x;
    const int total = VD_C * 64 * 64 * 64;
    if (idx >= total) return;
    int z = idx & 63, y = (idx >> 6) & 63, x = (idx >> 12) & 63, c = idx >> 18;
    const float* b = g + ((((size_t)c * 128 + 2 * x) * 128 + 2 * y) * 128 + 2 * z);
    float2 a0 = *(const float2*)(b);
    float2 a1 = *(const float2*)(b + 128);
    float2 a2 = *(const float2*)(b + 16384);
    float2 a3 = *(const float2*)(b + 16384 + 128);
    g_pool2[idx] = (a0.x + a0.y + a1.x + a1.y + a2.x + a2.y + a3.x + a3.y) * 0.125f;
}

__global__ void pool4_kernel() {
    int idx = blockIdx.x * blockDim.x + threadIdx.x;
    const int total = VD_C * 32 * 32 * 32;
    if (idx >= total) return;
    int z = idx & 31, y = (idx >> 5) & 31, x = (idx >> 10) & 31, c = idx >> 15;
    const float* b = g_pool2 + ((((size_t)c * 64 + 2 * x) * 64 + 2 * y) * 64 + 2 * z);
    float2 a0 = *(const float2*)(b);
    float2 a1 = *(const float2*)(b + 64);
    float2 a2 = *(const float2*)(b + 4096);
    float2 a3 = *(const float2*)(b + 4096 + 64);
    g_pool4[idx] = (a0.x + a0.y + a1.x + a1.y + a2.x + a2.y + a3.x + a3.y) * 0.125f;
}

// ---------------- timenet (tiny, runs once) ----------------
__global__ void timenet_kernel(const float* __restrict__ ft,
                               const float* __restrict__ w0, const float* __restrict__ b0,
                               const float* __restrict__ w1, const float* __restrict__ b1) {
    __shared__ float temb[9];
    __shared__ float h[128];
    int tid = threadIdx.x;
    if (tid == 0) {
        float t = ft[0];
        temb[0] = t;
        #pragma unroll
        for (int k = 0; k < 4; ++k) {
            temb[1 + k] = sinf(t * (float)(1 << k));
            temb[5 + k] = cosf(t * (float)(1 << k));
        }
    }
    __syncthreads();
    {
        float v = b0[tid];
        #pragma unroll
        for (int k = 0; k < 9; ++k) v = fmaf(temb[k], w0[k * 128 + tid], v);
        h[tid] = fmaxf(v, 0.f);
    }
    __syncthreads();
    if (tid < 60) {
        float v = b1[tid];
        for (int k = 0; k < 128; ++k) v = fmaf(h[k], w1[k * 60 + tid], v);
        g_tf[tid] = v;
    }
}

// ---------------- trilerp helpers ----------------
__device__ __forceinline__ void tri_setup(const float* pd, int D, int* ii, float* ff) {
    float dim = (float)(D - 1);
    float hi = dim - 1e-4f;
    #pragma unroll
    for (int c = 0; c < 3; ++c) {
        float t = (pd[c] + 1.f) * 0.5f * dim;
        t = fminf(fmaxf(t, 0.f), hi);
        float fl = floorf(t);
        ii[c] = (int)fl;
        ff[c] = t - fl;
    }
}

__device__ __forceinline__ float tri_gather(const float* __restrict__ g, int D,
                                            int ix, int iy, int iz,
                                            float fx, float fy, float fz) {
    size_t sx = (size_t)D * D;
    int sy = D;
    const float* b = g + (size_t)ix * sx + (size_t)iy * sy + iz;
    float v000 = __ldg(b),            v001 = __ldg(b + 1);
    float v010 = __ldg(b + sy),       v011 = __ldg(b + sy + 1);
    float v100 = __ldg(b + sx),       v101 = __ldg(b + sx + 1);
    float v110 = __ldg(b + sx + sy),  v111 = __ldg(b + sx + sy + 1);
    float c00 = v000 + (v001 - v000) * fz;
    float c01 = v010 + (v011 - v010) * fz;
    float c10 = v100 + (v101 - v100) * fz;
    float c11 = v110 + (v111 - v110) * fz;
    float c0 = c00 + (c01 - c00) * fy;
    float c1 = c10 + (c11 - c10) * fy;
    return c0 + (c1 - c0) * fx;
}

// ---------------- register-tiled f32x2 GEMM layer ----------------
// 64 points x OUT cols; 256 threads: ci = tid&15 (CP cols), pi = tid>>4 (4 points)
// Weight tiles double-buffered in smem via cp.async.
// INP = padded K (multiple of 16, x cols [INA,INP) must be zero in xs)
// INA = actual K (weight rows >= INA are zero-filled on load)
template <int OUT, int ACT>
__device__ __forceinline__ void mlp_layer(
    const float* __restrict__ W, const float* __restrict__ bias,
    const float* __restrict__ xs, int xp, int INA, int INP,
    float* __restrict__ ys, int yp,
    float* __restrict__ ws, int tid) {
    constexpr int CP = OUT / 16;   // 8 or 4 columns per thread
    constexpr int NP = CP / 2;     // f32x2 pairs per row
    const int ci = tid & 15;
    const int pi = tid >> 4;
    unsigned long long acc[4][NP];
    #pragma unroll
    for (int r = 0; r < 4; ++r)
        #pragma unroll
        for (int j = 0; j < NP; ++j) acc[r][j] = 0ull;

    const int ntiles = INP / KT;
    constexpr int CHUNKS = (KT * OUT) / 4;   // 16B chunks per tile

    // tile loader: cp.async with zero-fill for rows >= INA
    auto load_tile = [&](int t, int buf) {
        const float* src_base = W + (size_t)t * KT * OUT;
        float* dst_base = ws + buf * (KT * 128);
        int rem_floats = (INA - t * KT) * OUT;   // >0 for valid tiles
        #pragma unroll
        for (int c16 = tid; c16 < CHUNKS; c16 += NTHREADS) {
            const float* src = src_base + c16 * 4;
            int sz = ((c16 * 4) < rem_floats) ? 16 : 0;
            if (sz == 0) src = W;  // keep address valid
            unsigned dst = (unsigned)__cvta_generic_to_shared(dst_base + c16 * 4);
            asm volatile("cp.async.ca.shared.global [%0], [%1], 16, %2;"
                         :: "r"(dst), "l"(src), "r"(sz));
        }
        asm volatile("cp.async.commit_group;");
    };

    load_tile(0, 0);
    asm volatile("cp.async.wait_group 0;");
    __syncthreads();

    for (int t = 0; t < ntiles; ++t) {
        const int buf = t & 1;
        if (t + 1 < ntiles) load_tile(t + 1, buf ^ 1);
        const float* xb = xs + (size_t)(pi * 4) * xp + t * KT;
        const float* wb = ws + buf * (KT * 128);
        #pragma unroll
        for (int k4 = 0; k4 < KT; k4 += 4) {
            float4 xv[4];
            #pragma unroll
            for (int r = 0; r < 4; ++r)
                xv[r] = *reinterpret_cast<const float4*>(xb + r * xp + k4);
            #pragma unroll
            for (int kk = 0; kk < 4; ++kk) {
                unsigned long long xx[4];
                #pragma unroll
                for (int r = 0; r < 4; ++r) {
                    float xsv = (kk == 0) ? xv[r].x : (kk == 1) ? xv[r].y
                              : (kk == 2) ? xv[r].z : xv[r].w;
                    xx[r] = dup2(xsv);
                }
                const ulonglong2* wr = reinterpret_cast<const ulonglong2*>(
                    wb + (k4 + kk) * OUT + ci * CP);
                #pragma unroll
                for (int q = 0; q < NP / 2; ++q) {
                    ulonglong2 w2 = wr[q];
                    #pragma unroll
                    for (int r = 0; r < 4; ++r) {
                        ffma2(acc[r][2 * q],     xx[r], w2.x);
                        ffma2(acc[r][2 * q + 1], xx[r], w2.y);
                    }
                }
            }
        }
        asm volatile("cp.async.wait_group 0;");
        __syncthreads();
    }

    #pragma unroll
    for (int j = 0; j < NP; ++j) {
        float b0 = __ldg(bias + ci * CP + 2 * j);
        float b1 = __ldg(bias + ci * CP + 2 * j + 1);
        #pragma unroll
        for (int r = 0; r < 4; ++r) {
            float2 p = *reinterpret_cast<float2*>(&acc[r][j]);
            float v0 = p.x + b0, v1 = p.y + b1;
            if (ACT) { v0 = fmaxf(v0, 0.f); v1 = fmaxf(v1, 0.f); }
            const int row = pi * 4 + r;
            ys[(size_t)row * yp + ci * CP + 2 * j]     = v0;
            ys[(size_t)row * yp + ci * CP + 2 * j + 1] = v1;
        }
    }
}

// ---------------- fused main kernel: one block = one ray ----------------
__global__ void __launch_bounds__(NTHREADS, 2)
voxelmlp_main(const float* __restrict__ ray_pts,
              const float* __restrict__ viewdirs,
              const float* __restrict__ feature,
              const float* __restrict__ density,
              const float* __restrict__ dt_w0, const float* __restrict__ dt_b0,
              const float* __restrict__ dt_w1, const float* __restrict__ dt_b1,
              const float* __restrict__ dt_wo, const float* __restrict__ dt_bo,
              const float* __restrict__ fn_w0, const float* __restrict__ fn_b0,
              const float* __restrict__ dec_wf, const float* __restrict__ dec_bf,
              const float* __restrict__ dec_w0, const float* __restrict__ dec_b0,
              const float* __restrict__ dec_w1, const float* __restrict__ dec_b1,
              float* __restrict__ out) {
    extern __shared__ float sm[];
    float* A     = sm;                    // [64][212]
    float* Bb    = A + 64 * AP;           // [64][132]
    float* WS    = Bb + 64 * BP;          // [2][16][128]
    float* PD    = WS + 2 * KT * 128;     // [64][3]
    float* ALP   = PD + 192;              // [64]
    float* WGT   = ALP + 64;              // [64]
    float* RGB   = WGT + 64;              // [64][3]
    float* VE    = RGB + 192;             // [24]
    float* ALAST = VE + 24;               // [8]
    int*   TI    = reinterpret_cast<int*>(ALAST + 8);   // [64][3]
    float* TFR   = reinterpret_cast<float*>(TI + 192);  // [64][3]

    const int tid   = threadIdx.x;
    const int ray   = blockIdx.x;
    const int gbase = ray * PPR_C;

    // ---- phase 0: deform-net input X = [pts_emb(27), tf(60)], pad -> 96 ----
    if (tid < 64) {
        const int p = tid;
        float* row = A + p * AP;
        #pragma unroll
        for (int d = 0; d < 3; ++d) {
            float v = ray_pts[(size_t)(gbase + p) * 3 + d];
            row[d] = v;
            #pragma unroll
            for (int k = 0; k < 4; ++k) {
                float s, c;
                __sincosf(v * (float)(1 << k), &s, &c);
                row[3 + d * 4 + k]  = s;
                row[15 + d * 4 + k] = c;
            }
        }
    }
    if (tid >= 64 && tid < 67) {  // view embedding, once per ray
        const int d = tid - 64;
        float v = viewdirs[(size_t)ray * 3 + d];
        VE[d] = v;
        #pragma unroll
        for (int k = 0; k < 3; ++k) {
            float s, c;
            __sincosf(v * (float)(1 << k), &s, &c);
            VE[3 + d * 3 + k]  = s;
            VE[12 + d * 3 + k] = c;
        }
    }
    for (int i = tid; i < 64 * 60; i += NTHREADS) {
        int p = i & 63, j = i >> 6;
        A[p * AP + 27 + j] = g_tf[j];
    }
    for (int i = tid; i < 64 * 9; i += NTHREADS) {
        int p = i & 63, j = i >> 6;
        A[p * AP + 87 + j] = 0.f;
    }
    __syncthreads();

    // ---- deformation net ----
    mlp_layer<128, 1>(dt_w0, dt_b0, A, AP, 87, 96, Bb, BP, WS, tid);
    __syncthreads();
    mlp_layer<128, 1>(dt_w1, dt_b1, Bb, BP, 128, 128, A, AP, WS, tid);
    __syncthreads();

    {   // dx = H @ dt_wo + dt_bo ; pts_d = ray_pts + dx  (quad-parallel dot)
        const int p  = tid >> 2;
        const int l4 = tid & 3;
        float d0 = 0.f, d1 = 0.f, d2 = 0.f;
        const float* row = A + p * AP;
        #pragma unroll 8
        for (int k = l4; k < 128; k += 4) {
            float h = row[k];
            d0 = fmaf(h, __ldg(dt_wo + k * 3 + 0), d0);
            d1 = fmaf(h, __ldg(dt_wo + k * 3 + 1), d1);
            d2 = fmaf(h, __ldg(dt_wo + k * 3 + 2), d2);
        }
        d0 += __shfl_xor_sync(0xffffffffu, d0, 1);
        d0 += __shfl_xor_sync(0xffffffffu, d0, 2);
        d1 += __shfl_xor_sync(0xffffffffu, d1, 1);
        d1 += __shfl_xor_sync(0xffffffffu, d1, 2);
        d2 += __shfl_xor_sync(0xffffffffu, d2, 1);
        d2 += __shfl_xor_sync(0xffffffffu, d2, 2);
        if (l4 == 0) {
            PD[p * 3 + 0] = ray_pts[(size_t)(gbase + p) * 3 + 0] + d0 + __ldg(dt_bo + 0);
            PD[p * 3 + 1] = ray_pts[(size_t)(gbase + p) * 3 + 1] + d1 + __ldg(dt_bo + 1);
            PD[p * 3 + 2] = ray_pts[(size_t)(gbase + p) * 3 + 2] + d2 + __ldg(dt_bo + 2);
        }
    }
    __syncthreads();

    // ---- density -> alpha ----
    if (tid < 64) {
        const int p = tid;
        int ii[3]; float ff[3];
        tri_setup(PD + p * 3, GRID_C, ii, ff);
        float dens = tri_gather(density, GRID_C, ii[0], ii[1], ii[2], ff[0], ff[1], ff[2]);
        float x = dens + ACT_SHIFT_C;
        float sp = (x > 20.f) ? x : log1pf(__expf(x));
        ALP[p] = 1.f - __expf(-sp * 0.5f);
    }
    __syncthreads();
    if (tid == 0) {  // per-ray exclusive cumprod
        float T = 1.f;
        for (int i = 0; i < PPR_C; ++i) {
            float a = ALP[i];
            WGT[i] = a * T;
            T *= (1.f - a);
        }
        ALAST[0] = T;
    }

    // ---- 3-scale feature trilerp into X2 cols [0,36) ----
    #pragma unroll 1
    for (int s = 0; s < 3; ++s) {
        const int D = GRID_C >> s;
        if (tid < 64) {
            int ii[3]; float ff[3];
            tri_setup(PD + tid * 3, D, ii, ff);
            TI[tid * 3 + 0] = ii[0]; TI[tid * 3 + 1] = ii[1]; TI[tid * 3 + 2] = ii[2];
            TFR[tid * 3 + 0] = ff[0]; TFR[tid * 3 + 1] = ff[1]; TFR[tid * 3 + 2] = ff[2];
        }
        __syncthreads();
        const float* gp = (s == 0) ? feature : ((s == 1) ? (const float*)g_pool2
                                                         : (const float*)g_pool4);
        const size_t csz = (size_t)D * D * D;
        for (int i = tid; i < 64 * VD_C; i += NTHREADS) {
            int p = i & 63, c = i >> 6;
            float v = tri_gather(gp + (size_t)c * csz, D,
                                 TI[p * 3 + 0], TI[p * 3 + 1], TI[p * 3 + 2],
                                 TFR[p * 3 + 0], TFR[p * 3 + 1], TFR[p * 3 + 2]);
            A[p * AP + s * 12 + c] = v;
        }
        __syncthreads();
    }

    // ---- featurenet input X2 = [sin_emb(feat,2)(180), sin_emb(pts_d,4)(27)] ----
    for (int i = tid; i < 64 * 36; i += NTHREADS) {
        int p = i & 63, d = i >> 6;
        float* row = A + p * AP;
        float f = row[d];
        float s1, c1, s2, c2;
        __sincosf(f, &s1, &c1);
        __sincosf(2.f * f, &s2, &c2);
        row[36 + 2 * d]  = s1;  row[37 + 2 * d]  = s2;
        row[108 + 2 * d] = c1;  row[109 + 2 * d] = c2;
    }
    if (tid < 64) {
        const int p = tid;
        float* row = A + p * AP;
        #pragma unroll
        for (int d = 0; d < 3; ++d) {
            float v = PD[p * 3 + d];
            row[180 + d] = v;
            #pragma unroll
            for (int k = 0; k < 4; ++k) {
                float s, c;
                __sincosf(v * (float)(1 << k), &s, &c);
                row[183 + d * 4 + k] = s;
                row[195 + d * 4 + k] = c;
            }
        }
        row[207] = 0.f;
    }
    __syncthreads();

    // ---- featurenet + decoder ----
    mlp_layer<128, 1>(fn_w0, fn_b0, A, AP, 207, 208, Bb, BP, WS, tid);
    __syncthreads();
    mlp_layer<128, 0>(dec_wf, dec_bf, Bb, BP, 128, 128, A, AP, WS, tid);
    __syncthreads();
    if (tid < 64) {  // append vemb; pad to 160
        float* row = A + tid * AP;
        #pragma unroll
        for (int j = 0; j < 21; ++j) row[128 + j] = VE[j];
        #pragma unroll
        for (int j = 149; j < 160; ++j) row[j] = 0.f;
    }
    __syncthreads();
    mlp_layer<64, 1>(dec_w0, dec_b0, A, AP, 149, 160, Bb, BP, WS, tid);
    __syncthreads();

    {   // final 64->3 + sigmoid (quad-parallel)
        const int p  = tid >> 2;
        const int l4 = tid & 3;
        float r0 = 0.f, r1 = 0.f, r2 = 0.f;
        const float* row = Bb + p * BP;
        #pragma unroll 4
        for (int k = l4; k < 64; k += 4) {
            float h = row[k];
            r0 = fmaf(h, __ldg(dec_w1 + k * 3 + 0), r0);
            r1 = fmaf(h, __ldg(dec_w1 + k * 3 + 1), r1);
            r2 = fmaf(h, __ldg(dec_w1 + k * 3 + 2), r2);
        }
        r0 += __shfl_xor_sync(0xffffffffu, r0, 1);
        r0 += __shfl_xor_sync(0xffffffffu, r0, 2);
        r1 += __shfl_xor_sync(0xffffffffu, r1, 1);
        r1 += __shfl_xor_sync(0xffffffffu, r1, 2);
        r2 += __shfl_xor_sync(0xffffffffu, r2, 1);
        r2 += __shfl_xor_sync(0xffffffffu, r2, 2);
        if (l4 == 0) {
            r0 += __ldg(dec_b1 + 0);
            r1 += __ldg(dec_b1 + 1);
            r2 += __ldg(dec_b1 + 2);
            RGB[p * 3 + 0] = 1.f / (1.f + __expf(-r0));
            RGB[p * 3 + 1] = 1.f / (1.f + __expf(-r1));
            RGB[p * 3 + 2] = 1.f / (1.f + __expf(-r2));
        }
    }
    __syncthreads();

    if (tid < 3) {  // composite with white background
        float s = ALAST[0];
        for (int p = 0; p < PPR_C; ++p) s = fmaf(WGT[p], RGB[p * 3 + tid], s);
        out[(size_t)ray * 3 + tid] = s;
    }
}

// ---------------- launch ----------------
extern "C" void kernel_launch(void* const* d_in, const int* in_sizes, int n_in,
                              void* d_out, int out_size) {
    (void)in_sizes; (void)n_in; (void)out_size;
    const float* ray_pts    = (const float*)d_in[0];
    const float* viewdirs   = (const float*)d_in[1];
    const float* frame_time = (const float*)d_in[2];
    const float* feature    = (const float*)d_in[3];
    const float* density    = (const float*)d_in[4];
    const float* tn_w0 = (const float*)d_in[5];
    const float* tn_b0 = (const float*)d_in[6];
    const float* tn_w1 = (const float*)d_in[7];
    const float* tn_b1 = (const float*)d_in[8];
    const float* dt_w0 = (const float*)d_in[9];
    const float* dt_b0 = (const float*)d_in[10];
    const float* dt_w1 = (const float*)d_in[11];
    const float* dt_b1 = (const float*)d_in[12];
    const float* dt_wo = (const float*)d_in[13];
    const float* dt_bo = (const float*)d_in[14];
    const float* fn_w0 = (const float*)d_in[15];
    const float* fn_b0 = (const float*)d_in[16];
    const float* dec_wf = (const float*)d_in[17];
    const float* dec_bf = (const float*)d_in[18];
    const float* dec_w0 = (const float*)d_in[19];
    const float* dec_b0 = (const float*)d_in[20];
    const float* dec_w1 = (const float*)d_in[21];
    const float* dec_b1 = (const float*)d_in[22];
    float* out = (float*)d_out;

    cudaFuncSetAttribute(voxelmlp_main, cudaFuncAttributeMaxDynamicSharedMemorySize,
                         SMEM_BYTES);

    {
        const int total = VD_C * 64 * 64 * 64;
        pool2_kernel<<<(total + 255) / 256, 256>>>(feature);
    }
    {
        const int total = VD_C * 32 * 32 * 32;
        pool4_kernel<<<(total + 255) / 256, 256>>>();
    }
    timenet_kernel<<<1, 128>>>(frame_time, tn_w0, tn_b0, tn_w1, tn_b1);

    voxelmlp_main<<<N_RAYS_C, NTHREADS, SMEM_BYTES>>>(
        ray_pts, viewdirs, feature, density,
        dt_w0, dt_b0, dt_w1, dt_b1, dt_wo, dt_bo,
        fn_w0, fn_b0, dec_wf, dec_bf,
        dec_w0, dec_b0, dec_w1, dec_b1,
        out);
}

// round 12
// speedup vs baseline: 1.2885x; 1.2278x over previous
#include <cuda_runtime.h>
#include <cstdint>
#include <math.h>

// ---------------- problem constants ----------------
#define N_RAYS_C   4096
#define PPR_C      64
#define VD_C       12
#define GRID_C     128
#define ACT_SHIFT_C (-4.5951199f)   // log(1/(1-0.01) - 1)

#define AP 212
#define BP 132
#define KT 16
#define NTHREADS 256

// ---- smem layout (floats) ----
#define OFF_A     0
#define OFF_B     (64*AP)                    // 13568
#define OFF_WS    (OFF_B + 64*BP)            // 22016
#define OFF_W3    (OFF_WS + 2*KT*128)        // 26112 (dt_wo 384 + bias 3)
#define OFF_W3B   (OFF_W3 + 388)             // 26500 (dec_w1 192 + bias 3)
#define OFF_PD    (OFF_W3B + 196)            // 26696
#define OFF_ALP   (OFF_PD + 192)
#define OFF_WGT   (OFF_ALP + 64)
#define OFF_RGB   (OFF_WGT + 64)
#define OFF_VE    (OFF_RGB + 192)
#define OFF_ALAST (OFF_VE + 24)
#define OFF_TI    (OFF_ALAST + 8)
#define OFF_TFR   (OFF_TI + 192)
#define OFF_MB    (OFF_TFR + 192)            // 27624 (2 x u64 mbarriers)
#define SMEM_FLOATS (OFF_MB + 4)
#define SMEM_BYTES  (SMEM_FLOATS * 4)

// ---------------- device scratch (static: no allocation) ----------------
__device__ float g_feat_t[(size_t)GRID_C * GRID_C * GRID_C * VD_C];  // [X,Y,Z,C]
__device__ float g_pool2t[(size_t)64 * 64 * 64 * VD_C];
__device__ float g_pool4t[(size_t)32 * 32 * 32 * VD_C];
__device__ float g_tf[64];   // 60 used

// ---------------- f32x2 / ptx helpers ----------------
__device__ __forceinline__ void ffma2(unsigned long long& d, unsigned long long a,
                                      unsigned long long b) {
    asm("fma.rn.f32x2 %0, %1, %2, %0;" : "+l"(d) : "l"(a), "l"(b));
}
__device__ __forceinline__ unsigned long long dup2(float x) {
    unsigned long long r;
    asm("mov.b64 %0, {%1, %1};" : "=l"(r) : "f"(x));
    return r;
}
__device__ __forceinline__ uint32_t smem_u32(const void* p) {
    return (uint32_t)__cvta_generic_to_shared(p);
}
__device__ __forceinline__ void mbar_init(uint32_t a, uint32_t cnt) {
    asm volatile("mbarrier.init.shared.b64 [%0], %1;" :: "r"(a), "r"(cnt) : "memory");
}
__device__ __forceinline__ void mbar_expect(uint32_t a, uint32_t bytes) {
    asm volatile("mbarrier.arrive.expect_tx.shared.b64 _, [%0], %1;"
                 :: "r"(a), "r"(bytes) : "memory");
}
__device__ __forceinline__ void mbar_wait(uint32_t a, uint32_t parity) {
    asm volatile(
        "{\n\t"
        ".reg .pred P;\n"
        "LW%=:\n\t"
        "mbarrier.try_wait.parity.acquire.cta.shared::cta.b64 P, [%0], %1;\n\t"
        "@!P bra LW%=;\n\t"
        "}"
        :: "r"(a), "r"(parity) : "memory");
}
__device__ __forceinline__ void bulk_g2s(uint32_t dst, const float* src,
                                         uint32_t bytes, uint32_t mbar) {
    asm volatile(
        "cp.async.bulk.shared::cluster.global.mbarrier::complete_tx::bytes "
        "[%0], [%1], %2, [%3];"
        :: "r"(dst), "l"(src), "r"(bytes), "r"(mbar) : "memory");
}

// ---------------- grid transpose + pooling (transposed layouts) ----------------
__global__ void transpose_feat(const float* __restrict__ f) {
    int v = blockIdx.x * blockDim.x + threadIdx.x;
    const int V = GRID_C * GRID_C * GRID_C;
    if (v >= V) return;
    float vals[VD_C];
    #pragma unroll
    for (int c = 0; c < VD_C; ++c) vals[c] = __ldg(f + (size_t)c * V + v);
    float* dst = g_feat_t + (size_t)v * VD_C;
    #pragma unroll
    for (int q = 0; q < 3; ++q)
        *reinterpret_cast<float4*>(dst + q * 4) =
            make_float4(vals[q * 4], vals[q * 4 + 1], vals[q * 4 + 2], vals[q * 4 + 3]);
}

__global__ void pool2t_kernel() {
    int v = blockIdx.x * blockDim.x + threadIdx.x;
    if (v >= 64 * 64 * 64) return;
    int z = v & 63, y = (v >> 6) & 63, x = v >> 12;
    float acc[VD_C];
    #pragma unroll
    for (int c = 0; c < VD_C; ++c) acc[c] = 0.f;
    #pragma unroll
    for (int d = 0; d < 8; ++d) {
        int dx = d >> 2, dy = (d >> 1) & 1, dz = d & 1;
        const float* s = g_feat_t +
            ((((size_t)(2 * x + dx) * 128 + (2 * y + dy)) * 128 + (2 * z + dz)) * VD_C);
        #pragma unroll
        for (int q = 0; q < 3; ++q) {
            float4 b = *reinterpret_cast<const float4*>(s + q * 4);
            acc[q * 4 + 0] += b.x; acc[q * 4 + 1] += b.y;
            acc[q * 4 + 2] += b.z; acc[q * 4 + 3] += b.w;
        }
    }
    float* dst = g_pool2t + (size_t)v * VD_C;
    #pragma unroll
    for (int q = 0; q < 3; ++q)
        *reinterpret_cast<float4*>(dst + q * 4) =
            make_float4(acc[q * 4] * 0.125f, acc[q * 4 + 1] * 0.125f,
                        acc[q * 4 + 2] * 0.125f, acc[q * 4 + 3] * 0.125f);
}

__global__ void pool4t_kernel() {
    int v = blockIdx.x * blockDim.x + threadIdx.x;
    if (v >= 32 * 32 * 32) return;
    int z = v & 31, y = (v >> 5) & 31, x = v >> 10;
    float acc[VD_C];
    #pragma unroll
    for (int c = 0; c < VD_C; ++c) acc[c] = 0.f;
    #pragma unroll
    for (int d = 0; d < 8; ++d) {
        int dx = d >> 2, dy = (d >> 1) & 1, dz = d & 1;
        const float* s = g_pool2t +
            ((((size_t)(2 * x + dx) * 64 + (2 * y + dy)) * 64 + (2 * z + dz)) * VD_C);
        #pragma unroll
        for (int q = 0; q < 3; ++q) {
            float4 b = *reinterpret_cast<const float4*>(s + q * 4);
            acc[q * 4 + 0] += b.x; acc[q * 4 + 1] += b.y;
            acc[q * 4 + 2] += b.z; acc[q * 4 + 3] += b.w;
        }
    }
    float* dst = g_pool4t + (size_t)v * VD_C;
    #pragma unroll
    for (int q = 0; q < 3; ++q)
        *reinterpret_cast<float4*>(dst + q * 4) =
            make_float4(acc[q * 4] * 0.125f, acc[q * 4 + 1] * 0.125f,
                        acc[q * 4 + 2] * 0.125f, acc[q * 4 + 3] * 0.125f);
}

// ---------------- timenet (tiny, runs once) ----------------
__global__ void timenet_kernel(const float* __restrict__ ft,
                               const float* __restrict__ w0, const float* __restrict__ b0,
                               const float* __restrict__ w1, const float* __restrict__ b1) {
    __shared__ float temb[9];
    __shared__ float h[128];
    int tid = threadIdx.x;
    if (tid == 0) {
        float t = ft[0];
        temb[0] = t;
        #pragma unroll
        for (int k = 0; k < 4; ++k) {
            temb[1 + k] = sinf(t * (float)(1 << k));
            temb[5 + k] = cosf(t * (float)(1 << k));
        }
    }
    __syncthreads();
    {
        float v = b0[tid];
        #pragma unroll
        for (int k = 0; k < 9; ++k) v = fmaf(temb[k], w0[k * 128 + tid], v);
        h[tid] = fmaxf(v, 0.f);
    }
    __syncthreads();
    if (tid < 60) {
        float v = b1[tid];
        for (int k = 0; k < 128; ++k) v = fmaf(h[k], w1[k * 60 + tid], v);
        g_tf[tid] = v;
    }
}

// ---------------- trilerp setup ----------------
__device__ __forceinline__ void tri_setup(const float* pd, int D, int* ii, float* ff) {
    float dim = (float)(D - 1);
    float hi = dim - 1e-4f;
    #pragma unroll
    for (int c = 0; c < 3; ++c) {
        float t = (pd[c] + 1.f) * 0.5f * dim;
        t = fminf(fmaxf(t, 0.f), hi);
        float fl = floorf(t);
        ii[c] = (int)fl;
        ff[c] = t - fl;
    }
}

__device__ __forceinline__ float tri_gather1(const float* __restrict__ g, int D,
                                             int ix, int iy, int iz,
                                             float fx, float fy, float fz) {
    size_t sx = (size_t)D * D;
    int sy = D;
    const float* b = g + (size_t)ix * sx + (size_t)iy * sy + iz;
    float v000 = __ldg(b),            v001 = __ldg(b + 1);
    float v010 = __ldg(b + sy),       v011 = __ldg(b + sy + 1);
    float v100 = __ldg(b + sx),       v101 = __ldg(b + sx + 1);
    float v110 = __ldg(b + sx + sy),  v111 = __ldg(b + sx + sy + 1);
    float c00 = v000 + (v001 - v000) * fz;
    float c01 = v010 + (v011 - v010) * fz;
    float c10 = v100 + (v101 - v100) * fz;
    float c11 = v110 + (v111 - v110) * fz;
    float c0 = c00 + (c01 - c00) * fy;
    float c1 = c10 + (c11 - c10) * fy;
    return c0 + (c1 - c0) * fx;
}

__device__ __forceinline__ float4 lerp4(float4 a, float4 b, float t) {
    return make_float4(a.x + (b.x - a.x) * t, a.y + (b.y - a.y) * t,
                       a.z + (b.z - a.z) * t, a.w + (b.w - a.w) * t);
}

// ---------------- register-tiled f32x2 GEMM with TMA-bulk weight staging ------
// 64 points x OUT cols; 256 threads: ci = tid&15 (CP cols), pi = tid>>4 (4 pts)
template <int OUT, int ACT>
__device__ __forceinline__ void mlp_layer(
    const float* __restrict__ W, const float* __restrict__ bias,
    const float* __restrict__ xs, int xp, int INA, int INP,
    float* __restrict__ ys, int yp,
    float* __restrict__ ws, uint32_t mb0, uint32_t mb1,
    int& ph0, int& ph1, int tid) {
    constexpr int CP = OUT / 16;
    constexpr int NP = CP / 2;
    const int ci = tid & 15;
    const int pi = tid >> 4;
    unsigned long long acc[4][NP];
    #pragma unroll
    for (int r = 0; r < 4; ++r)
        #pragma unroll
        for (int j = 0; j < NP; ++j) acc[r][j] = 0ull;

    const int ntiles = INP / KT;

    auto issue = [&](int t, int buf) {
        if (tid == 0) {
            int rows = INA - t * KT; if (rows > KT) rows = KT;
            uint32_t bytes = (uint32_t)rows * OUT * 4u;
            uint32_t mb = buf ? mb1 : mb0;
            mbar_expect(mb, bytes);
            bulk_g2s(smem_u32(ws + buf * (KT * 128)), W + (size_t)t * KT * OUT,
                     bytes, mb);
        }
    };

    issue(0, 0);
    for (int t = 0; t < ntiles; ++t) {
        const int buf = t & 1;
        if (buf == 0) { mbar_wait(mb0, (uint32_t)ph0); ph0 ^= 1; }
        else          { mbar_wait(mb1, (uint32_t)ph1); ph1 ^= 1; }
        __syncthreads();                       // all threads past previous tile
        if (t + 1 < ntiles) issue(t + 1, buf ^ 1);

        const float* xb = xs + (size_t)(pi * 4) * xp + t * KT;
        const float* wb = ws + buf * (KT * 128);
        #pragma unroll
        for (int k4 = 0; k4 < KT; k4 += 4) {
            float4 xv[4];
            #pragma unroll
            for (int r = 0; r < 4; ++r)
                xv[r] = *reinterpret_cast<const float4*>(xb + r * xp + k4);
            #pragma unroll
            for (int kk = 0; kk < 4; ++kk) {
                unsigned long long xx[4];
                #pragma unroll
                for (int r = 0; r < 4; ++r) {
                    float xsv = (kk == 0) ? xv[r].x : (kk == 1) ? xv[r].y
                              : (kk == 2) ? xv[r].z : xv[r].w;
                    xx[r] = dup2(xsv);
                }
                const ulonglong2* wr = reinterpret_cast<const ulonglong2*>(
                    wb + (k4 + kk) * OUT + ci * CP);
                #pragma unroll
                for (int q = 0; q < NP / 2; ++q) {
                    ulonglong2 w2 = wr[q];
                    #pragma unroll
                    for (int r = 0; r < 4; ++r) {
                        ffma2(acc[r][2 * q],     xx[r], w2.x);
                        ffma2(acc[r][2 * q + 1], xx[r], w2.y);
                    }
                }
            }
        }
    }

    #pragma unroll
    for (int j = 0; j < NP; ++j) {
        float b0 = __ldg(bias + ci * CP + 2 * j);
        float b1 = __ldg(bias + ci * CP + 2 * j + 1);
        #pragma unroll
        for (int r = 0; r < 4; ++r) {
            float2 p = *reinterpret_cast<float2*>(&acc[r][j]);
            float v0 = p.x + b0, v1 = p.y + b1;
            if (ACT) { v0 = fmaxf(v0, 0.f); v1 = fmaxf(v1, 0.f); }
            const int row = pi * 4 + r;
            ys[(size_t)row * yp + ci * CP + 2 * j]     = v0;
            ys[(size_t)row * yp + ci * CP + 2 * j + 1] = v1;
        }
    }
}

// ---------------- fused main kernel: one block = one ray ----------------
__global__ void __launch_bounds__(NTHREADS, 2)
voxelmlp_main(const float* __restrict__ ray_pts,
              const float* __restrict__ viewdirs,
              const float* __restrict__ density,
              const float* __restrict__ dt_w0, const float* __restrict__ dt_b0,
              const float* __restrict__ dt_w1, const float* __restrict__ dt_b1,
              const float* __restrict__ dt_wo, const float* __restrict__ dt_bo,
              const float* __restrict__ fn_w0, const float* __restrict__ fn_b0,
              const float* __restrict__ dec_wf, const float* __restrict__ dec_bf,
              const float* __restrict__ dec_w0, const float* __restrict__ dec_b0,
              const float* __restrict__ dec_w1, const float* __restrict__ dec_b1,
              float* __restrict__ out) {
    extern __shared__ float sm[];
    float* A     = sm + OFF_A;
    float* Bb    = sm + OFF_B;
    float* WS    = sm + OFF_WS;
    float* W3    = sm + OFF_W3;
    float* W3B   = sm + OFF_W3B;
    float* PD    = sm + OFF_PD;
    float* ALP   = sm + OFF_ALP;
    float* WGT   = sm + OFF_WGT;
    float* RGB   = sm + OFF_RGB;
    float* VE    = sm + OFF_VE;
    float* ALAST = sm + OFF_ALAST;
    int*   TI    = reinterpret_cast<int*>(sm + OFF_TI);
    float* TFR   = sm + OFF_TFR;
    const uint32_t mb0 = smem_u32(sm + OFF_MB);
    const uint32_t mb1 = mb0 + 8;

    const int tid   = threadIdx.x;
    const int ray   = blockIdx.x;
    const int gbase = ray * PPR_C;
    int ph0 = 0, ph1 = 0;

    // ---- init: zero weight buffers (stale-NaN guard), init mbarriers ----
    for (int i = tid; i < 2 * KT * 128; i += NTHREADS) WS[i] = 0.f;
    if (tid == 0) { mbar_init(mb0, 1); mbar_init(mb1, 1); }
    asm volatile("fence.proxy.async.shared::cta;" ::: "memory");

    // stage small weights to smem
    for (int i = tid; i < 128 * 3; i += NTHREADS) W3[i] = __ldg(dt_wo + i);
    if (tid < 3) W3[384 + tid] = __ldg(dt_bo + tid);
    for (int i = tid; i < 64 * 3; i += NTHREADS) W3B[i] = __ldg(dec_w1 + i);
    if (tid < 3) W3B[192 + tid] = __ldg(dec_b1 + tid);

    // ---- phase 0: deform input X = [pts_emb(27), tf(60)], pad -> 96 ----
    if (tid < 64) {
        const int p = tid;
        float* row = A + p * AP;
        #pragma unroll
        for (int d = 0; d < 3; ++d) {
            float v = ray_pts[(size_t)(gbase + p) * 3 + d];
            row[d] = v;
            float s, c;
            __sincosf(v, &s, &c);
            row[3 + d * 4]  = s;
            row[15 + d * 4] = c;
            #pragma unroll
            for (int k = 1; k < 4; ++k) {
                float s2 = 2.f * s * c;
                float c2 = fmaf(-2.f * s, s, 1.f);
                s = s2; c = c2;
                row[3 + d * 4 + k]  = s;
                row[15 + d * 4 + k] = c;
            }
        }
    }
    if (tid >= 64 && tid < 67) {  // view embedding
        const int d = tid - 64;
        float v = viewdirs[(size_t)ray * 3 + d];
        VE[d] = v;
        float s, c;
        __sincosf(v, &s, &c);
        VE[3 + d * 3]  = s;
        VE[12 + d * 3] = c;
        #pragma unroll
        for (int k = 1; k < 3; ++k) {
            float s2 = 2.f * s * c;
            float c2 = fmaf(-2.f * s, s, 1.f);
            s = s2; c = c2;
            VE[3 + d * 3 + k]  = s;
            VE[12 + d * 3 + k] = c;
        }
    }
    for (int i = tid; i < 64 * 60; i += NTHREADS) {
        int p = i & 63, j = i >> 6;
        A[p * AP + 27 + j] = g_tf[j];
    }
    for (int i = tid; i < 64 * 9; i += NTHREADS) {
        int p = i & 63, j = i >> 6;
        A[p * AP + 87 + j] = 0.f;
    }
    __syncthreads();

    // ---- deformation net ----
    mlp_layer<128, 1>(dt_w0, dt_b0, A, AP, 87, 96, Bb, BP, WS, mb0, mb1, ph0, ph1, tid);
    __syncthreads();
    mlp_layer<128, 1>(dt_w1, dt_b1, Bb, BP, 128, 128, A, AP, WS, mb0, mb1, ph0, ph1, tid);
    __syncthreads();

    {   // dx = H @ dt_wo + dt_bo (quad-parallel, weights from smem)
        const int p  = tid >> 2;
        const int l4 = tid & 3;
        float d0 = 0.f, d1 = 0.f, d2 = 0.f;
        const float* row = A + p * AP;
        #pragma unroll 8
        for (int k = l4; k < 128; k += 4) {
            float h = row[k];
            d0 = fmaf(h, W3[k * 3 + 0], d0);
            d1 = fmaf(h, W3[k * 3 + 1], d1);
            d2 = fmaf(h, W3[k * 3 + 2], d2);
        }
        d0 += __shfl_xor_sync(0xffffffffu, d0, 1);
        d0 += __shfl_xor_sync(0xffffffffu, d0, 2);
        d1 += __shfl_xor_sync(0xffffffffu, d1, 1);
        d1 += __shfl_xor_sync(0xffffffffu, d1, 2);
        d2 += __shfl_xor_sync(0xffffffffu, d2, 1);
        d2 += __shfl_xor_sync(0xffffffffu, d2, 2);
        if (l4 == 0) {
            PD[p * 3 + 0] = ray_pts[(size_t)(gbase + p) * 3 + 0] + d0 + W3[384];
            PD[p * 3 + 1] = ray_pts[(size_t)(gbase + p) * 3 + 1] + d1 + W3[385];
            PD[p * 3 + 2] = ray_pts[(size_t)(gbase + p) * 3 + 2] + d2 + W3[386];
        }
    }
    __syncthreads();

    // ---- density -> alpha ----
    if (tid < 64) {
        const int p = tid;
        int ii[3]; float ff[3];
        tri_setup(PD + p * 3, GRID_C, ii, ff);
        float dens = tri_gather1(density, GRID_C, ii[0], ii[1], ii[2],
                                 ff[0], ff[1], ff[2]);
        float x = dens + ACT_SHIFT_C;
        float sp = (x > 20.f) ? x : log1pf(__expf(x));
        ALP[p] = 1.f - __expf(-sp * 0.5f);
    }
    __syncthreads();
    if (tid == 0) {  // per-ray exclusive cumprod
        float T = 1.f;
        for (int i = 0; i < PPR_C; ++i) {
            float a = ALP[i];
            WGT[i] = a * T;
            T *= (1.f - a);
        }
        ALAST[0] = T;
    }

    // ---- 3-scale feature trilerp (transposed grids, float4 gathers) ----
    #pragma unroll 1
    for (int s = 0; s < 3; ++s) {
        const int D = GRID_C >> s;
        if (tid < 64) {
            int ii[3]; float ff[3];
            tri_setup(PD + tid * 3, D, ii, ff);
            TI[tid * 3 + 0] = ii[0]; TI[tid * 3 + 1] = ii[1]; TI[tid * 3 + 2] = ii[2];
            TFR[tid * 3 + 0] = ff[0]; TFR[tid * 3 + 1] = ff[1]; TFR[tid * 3 + 2] = ff[2];
        }
        __syncthreads();
        const float* gp = (s == 0) ? (const float*)g_feat_t
                        : (s == 1) ? (const float*)g_pool2t
                                   : (const float*)g_pool4t;
        {
            const int p = tid >> 2, q = tid & 3;
            if (q < 3) {
                int ix = TI[p * 3 + 0], iy = TI[p * 3 + 1], iz = TI[p * 3 + 2];
                float fx = TFR[p * 3 + 0], fy = TFR[p * 3 + 1], fz = TFR[p * 3 + 2];
                const size_t sy = (size_t)D * VD_C;
                const size_t sx = (size_t)D * sy;
                const float* b = gp + (size_t)ix * sx + (size_t)iy * sy
                               + (size_t)iz * VD_C + q * 4;
                float4 v000 = __ldg((const float4*)(b));
                float4 v001 = __ldg((const float4*)(b + VD_C));
                float4 v010 = __ldg((const float4*)(b + sy));
                float4 v011 = __ldg((const float4*)(b + sy + VD_C));
                float4 v100 = __ldg((const float4*)(b + sx));
                float4 v101 = __ldg((const float4*)(b + sx + VD_C));
                float4 v110 = __ldg((const float4*)(b + sx + sy));
                float4 v111 = __ldg((const float4*)(b + sx + sy + VD_C));
                float4 c00 = lerp4(v000, v001, fz);
                float4 c01 = lerp4(v010, v011, fz);
                float4 c10 = lerp4(v100, v101, fz);
                float4 c11 = lerp4(v110, v111, fz);
                float4 c0 = lerp4(c00, c01, fy);
                float4 c1 = lerp4(c10, c11, fy);
                float4 r  = lerp4(c0, c1, fx);
                *reinterpret_cast<float4*>(A + p * AP + s * 12 + q * 4) = r;
            }
        }
        __syncthreads();
    }

    // ---- featurenet input: sin_emb(feat,2)(180) + sin_emb(pts_d,4)(27) ----
    for (int i = tid; i < 64 * 36; i += NTHREADS) {
        int p = i & 63, d = i >> 6;
        float* row = A + p * AP;
        float f = row[d];
        float s1, c1;
        __sincosf(f, &s1, &c1);
        float s2 = 2.f * s1 * c1;
        float c2 = fmaf(-2.f * s1, s1, 1.f);
        row[36 + 2 * d]  = s1;  row[37 + 2 * d]  = s2;
        row[108 + 2 * d] = c1;  row[109 + 2 * d] = c2;
    }
    if (tid < 64) {
        const int p = tid;
        float* row = A + p * AP;
        #pragma unroll
        for (int d = 0; d < 3; ++d) {
            float v = PD[p * 3 + d];
            row[180 + d] = v;
            float s, c;
            __sincosf(v, &s, &c);
            row[183 + d * 4] = s;
            row[195 + d * 4] = c;
            #pragma unroll
            for (int k = 1; k < 4; ++k) {
                float s2 = 2.f * s * c;
                float c2 = fmaf(-2.f * s, s, 1.f);
                s = s2; c = c2;
                row[183 + d * 4 + k] = s;
                row[195 + d * 4 + k] = c;
            }
        }
        row[207] = 0.f;
    }
    __syncthreads();

    // ---- featurenet + decoder ----
    mlp_layer<128, 1>(fn_w0, fn_b0, A, AP, 207, 208, Bb, BP, WS, mb0, mb1, ph0, ph1, tid);
    __syncthreads();
    mlp_layer<128, 0>(dec_wf, dec_bf, Bb, BP, 128, 128, A, AP, WS, mb0, mb1, ph0, ph1, tid);
    __syncthreads();
    if (tid < 64) {  // append vemb; pad to 160
        float* row = A + tid * AP;
        #pragma unroll
        for (int j = 0; j < 21; ++j) row[128 + j] = VE[j];
        #pragma unroll
        for (int j = 149; j < 160; ++j) row[j] = 0.f;
    }
    __syncthreads();
    mlp_layer<64, 1>(dec_w0, dec_b0, A, AP, 149, 160, Bb, BP, WS, mb0, mb1, ph0, ph1, tid);
    __syncthreads();

    {   // final 64->3 + sigmoid (quad-parallel, weights from smem)
        const int p  = tid >> 2;
        const int l4 = tid & 3;
        float r0 = 0.f, r1 = 0.f, r2 = 0.f;
        const float* row = Bb + p * BP;
        #pragma unroll 4
        for (int k = l4; k < 64; k += 4) {
            float h = row[k];
            r0 = fmaf(h, W3B[k * 3 + 0], r0);
            r1 = fmaf(h, W3B[k * 3 + 1], r1);
            r2 = fmaf(h, W3B[k * 3 + 2], r2);
        }
        r0 += __shfl_xor_sync(0xffffffffu, r0, 1);
        r0 += __shfl_xor_sync(0xffffffffu, r0, 2);
        r1 += __shfl_xor_sync(0xffffffffu, r1, 1);
        r1 += __shfl_xor_sync(0xffffffffu, r1, 2);
        r2 += __shfl_xor_sync(0xffffffffu, r2, 1);
        r2 += __shfl_xor_sync(0xffffffffu, r2, 2);
        if (l4 == 0) {
            r0 += W3B[192]; r1 += W3B[193]; r2 += W3B[194];
            RGB[p * 3 + 0] = 1.f / (1.f + __expf(-r0));
            RGB[p * 3 + 1] = 1.f / (1.f + __expf(-r1));
            RGB[p * 3 + 2] = 1.f / (1.f + __expf(-r2));
        }
    }
    __syncthreads();

    if (tid < 3) {  // composite with white background
        float s = ALAST[0];
        for (int p = 0; p < PPR_C; ++p) s = fmaf(WGT[p], RGB[p * 3 + tid], s);
        out[(size_t)ray * 3 + tid] = s;
    }
}

// ---------------- launch ----------------
extern "C" void kernel_launch(void* const* d_in, const int* in_sizes, int n_in,
                              void* d_out, int out_size) {
    (void)in_sizes; (void)n_in; (void)out_size;
    const float* ray_pts    = (const float*)d_in[0];
    const float* viewdirs   = (const float*)d_in[1];
    const float* frame_time = (const float*)d_in[2];
    const float* feature    = (const float*)d_in[3];
    const float* density    = (const float*)d_in[4];
    const float* tn_w0 = (const float*)d_in[5];
    const float* tn_b0 = (const float*)d_in[6];
    const float* tn_w1 = (const float*)d_in[7];
    const float* tn_b1 = (const float*)d_in[8];
    const float* dt_w0 = (const float*)d_in[9];
    const float* dt_b0 = (const float*)d_in[10];
    const float* dt_w1 = (const float*)d_in[11];
    const float* dt_b1 = (const float*)d_in[12];
    const float* dt_wo = (const float*)d_in[13];
    const float* dt_bo = (const float*)d_in[14];
    const float* fn_w0 = (const float*)d_in[15];
    const float* fn_b0 = (const float*)d_in[16];
    const float* dec_wf = (const float*)d_in[17];
    const float* dec_bf = (const float*)d_in[18];
    const float* dec_w0 = (const float*)d_in[19];
    const float* dec_b0 = (const float*)d_in[20];
    const float* dec_w1 = (const float*)d_in[21];
    const float* dec_b1 = (const float*)d_in[22];
    float* out = (float*)d_out;

    cudaFuncSetAttribute(voxelmlp_main, cudaFuncAttributeMaxDynamicSharedMemorySize,
                         SMEM_BYTES);

    {
        const int V = GRID_C * GRID_C * GRID_C;
        transpose_feat<<<(V + 255) / 256, 256>>>(feature);
    }
    pool2t_kernel<<<(64 * 64 * 64 + 255) / 256, 256>>>();
    pool4t_kernel<<<(32 * 32 * 32 + 255) / 256, 256>>>();
    timenet_kernel<<<1, 128>>>(frame_time, tn_w0, tn_b0, tn_w1, tn_b1);

    voxelmlp_main<<<N_RAYS_C, NTHREADS, SMEM_BYTES>>>(
        ray_pts, viewdirs, density,
        dt_w0, dt_b0, dt_w1, dt_b1, dt_wo, dt_bo,
        fn_w0, fn_b0, dec_wf, dec_bf,
        dec_w0, dec_b0, dec_w1, dec_b1,
        out);
}

// round 13
// speedup vs baseline: 1.2911x; 1.0020x over previous
#include <cuda_runtime.h>
#include <cstdint>
#include <math.h>

// ---------------- problem constants ----------------
#define N_RAYS_C   4096
#define PPR_C      64
#define VD_C       12
#define GRID_C     128
#define ACT_SHIFT_C (-4.5951199f)   // log(1/(1-0.01) - 1)

#define AP 212
#define BP 132
#define KT 16
#define NTHREADS 256

// ---- smem layout (floats) ----
#define OFF_A     0
#define OFF_B     (64*AP)                    // 13568
#define OFF_WS    (OFF_B + 64*BP)            // 22016
#define OFF_W3    (OFF_WS + 2*KT*128)        // 26112 (dt_wo 384 + bias 3)
#define OFF_W3B   (OFF_W3 + 388)             // 26500 (dec_w1 192 + bias 3)
#define OFF_PD    (OFF_W3B + 196)            // 26696
#define OFF_ALP   (OFF_PD + 192)
#define OFF_WGT   (OFF_ALP + 64)
#define OFF_RGB   (OFF_WGT + 64)
#define OFF_VE    (OFF_RGB + 192)
#define OFF_ALAST (OFF_VE + 24)
#define OFF_TI    (OFF_ALAST + 8)
#define OFF_TFR   (OFF_TI + 192)
#define OFF_MB    (OFF_TFR + 192)            // 27624 (2 x u64 mbarriers)
#define SMEM_FLOATS (OFF_MB + 4)
#define SMEM_BYTES  (SMEM_FLOATS * 4)

// ---------------- device scratch (static: no allocation) ----------------
__device__ float g_feat_t[(size_t)GRID_C * GRID_C * GRID_C * VD_C];  // [X,Y,Z,C]
__device__ float g_pool2t[(size_t)64 * 64 * 64 * VD_C];
__device__ float g_pool4t[(size_t)32 * 32 * 32 * VD_C];
__device__ float g_tf[64];   // 60 used

// ---------------- f32x2 / ptx helpers ----------------
__device__ __forceinline__ void ffma2(unsigned long long& d, unsigned long long a,
                                      unsigned long long b) {
    asm("fma.rn.f32x2 %0, %1, %2, %0;" : "+l"(d) : "l"(a), "l"(b));
}
__device__ __forceinline__ unsigned long long dup2(float x) {
    unsigned long long r;
    asm("mov.b64 %0, {%1, %1};" : "=l"(r) : "f"(x));
    return r;
}
__device__ __forceinline__ uint32_t smem_u32(const void* p) {
    return (uint32_t)__cvta_generic_to_shared(p);
}
__device__ __forceinline__ void mbar_init(uint32_t a, uint32_t cnt) {
    asm volatile("mbarrier.init.shared.b64 [%0], %1;" :: "r"(a), "r"(cnt) : "memory");
}
__device__ __forceinline__ void mbar_expect(uint32_t a, uint32_t bytes) {
    asm volatile("mbarrier.arrive.expect_tx.shared.b64 _, [%0], %1;"
                 :: "r"(a), "r"(bytes) : "memory");
}
__device__ __forceinline__ void mbar_wait(uint32_t a, uint32_t parity) {
    asm volatile(
        "{\n\t"
        ".reg .pred P;\n"
        "LW%=:\n\t"
        "mbarrier.try_wait.parity.acquire.cta.shared::cta.b64 P, [%0], %1;\n\t"
        "@!P bra LW%=;\n\t"
        "}"
        :: "r"(a), "r"(parity) : "memory");
}
__device__ __forceinline__ void bulk_g2s(uint32_t dst, const float* src,
                                         uint32_t bytes, uint32_t mbar) {
    asm volatile(
        "cp.async.bulk.shared::cluster.global.mbarrier::complete_tx::bytes "
        "[%0], [%1], %2, [%3];"
        :: "r"(dst), "l"(src), "r"(bytes), "r"(mbar) : "memory");
}

// ---------------- grid transpose + pooling (transposed layouts) ----------------
__global__ void transpose_feat(const float* __restrict__ f) {
    int v = blockIdx.x * blockDim.x + threadIdx.x;
    const int V = GRID_C * GRID_C * GRID_C;
    if (v >= V) return;
    float vals[VD_C];
    #pragma unroll
    for (int c = 0; c < VD_C; ++c) vals[c] = __ldg(f + (size_t)c * V + v);
    float* dst = g_feat_t + (size_t)v * VD_C;
    #pragma unroll
    for (int q = 0; q < 3; ++q)
        *reinterpret_cast<float4*>(dst + q * 4) =
            make_float4(vals[q * 4], vals[q * 4 + 1], vals[q * 4 + 2], vals[q * 4 + 3]);
}

__global__ void pool2t_kernel() {
    int v = blockIdx.x * blockDim.x + threadIdx.x;
    if (v >= 64 * 64 * 64) return;
    int z = v & 63, y = (v >> 6) & 63, x = v >> 12;
    float acc[VD_C];
    #pragma unroll
    for (int c = 0; c < VD_C; ++c) acc[c] = 0.f;
    #pragma unroll
    for (int d = 0; d < 8; ++d) {
        int dx = d >> 2, dy = (d >> 1) & 1, dz = d & 1;
        const float* s = g_feat_t +
            ((((size_t)(2 * x + dx) * 128 + (2 * y + dy)) * 128 + (2 * z + dz)) * VD_C);
        #pragma unroll
        for (int q = 0; q < 3; ++q) {
            float4 b = *reinterpret_cast<const float4*>(s + q * 4);
            acc[q * 4 + 0] += b.x; acc[q * 4 + 1] += b.y;
            acc[q * 4 + 2] += b.z; acc[q * 4 + 3] += b.w;
        }
    }
    float* dst = g_pool2t + (size_t)v * VD_C;
    #pragma unroll
    for (int q = 0; q < 3; ++q)
        *reinterpret_cast<float4*>(dst + q * 4) =
            make_float4(acc[q * 4] * 0.125f, acc[q * 4 + 1] * 0.125f,
                        acc[q * 4 + 2] * 0.125f, acc[q * 4 + 3] * 0.125f);
}

__global__ void pool4t_kernel() {
    int v = blockIdx.x * blockDim.x + threadIdx.x;
    if (v >= 32 * 32 * 32) return;
    int z = v & 31, y = (v >> 5) & 31, x = v >> 10;
    float acc[VD_C];
    #pragma unroll
    for (int c = 0; c < VD_C; ++c) acc[c] = 0.f;
    #pragma unroll
    for (int d = 0; d < 8; ++d) {
        int dx = d >> 2, dy = (d >> 1) & 1, dz = d & 1;
        const float* s = g_pool2t +
            ((((size_t)(2 * x + dx) * 64 + (2 * y + dy)) * 64 + (2 * z + dz)) * VD_C);
        #pragma unroll
        for (int q = 0; q < 3; ++q) {
            float4 b = *reinterpret_cast<const float4*>(s + q * 4);
            acc[q * 4 + 0] += b.x; acc[q * 4 + 1] += b.y;
            acc[q * 4 + 2] += b.z; acc[q * 4 + 3] += b.w;
        }
    }
    float* dst = g_pool4t + (size_t)v * VD_C;
    #pragma unroll
    for (int q = 0; q < 3; ++q)
        *reinterpret_cast<float4*>(dst + q * 4) =
            make_float4(acc[q * 4] * 0.125f, acc[q * 4 + 1] * 0.125f,
                        acc[q * 4 + 2] * 0.125f, acc[q * 4 + 3] * 0.125f);
}

// ---------------- timenet (tiny, runs once) ----------------
__global__ void timenet_kernel(const float* __restrict__ ft,
                               const float* __restrict__ w0, const float* __restrict__ b0,
                               const float* __restrict__ w1, const float* __restrict__ b1) {
    __shared__ float temb[9];
    __shared__ float h[128];
    int tid = threadIdx.x;
    if (tid == 0) {
        float t = ft[0];
        temb[0] = t;
        #pragma unroll
        for (int k = 0; k < 4; ++k) {
            temb[1 + k] = sinf(t * (float)(1 << k));
            temb[5 + k] = cosf(t * (float)(1 << k));
        }
    }
    __syncthreads();
    {
        float v = b0[tid];
        #pragma unroll
        for (int k = 0; k < 9; ++k) v = fmaf(temb[k], w0[k * 128 + tid], v);
        h[tid] = fmaxf(v, 0.f);
    }
    __syncthreads();
    if (tid < 60) {
        float v = b1[tid];
        for (int k = 0; k < 128; ++k) v = fmaf(h[k], w1[k * 60 + tid], v);
        g_tf[tid] = v;
    }
}

// ---------------- trilerp setup ----------------
__device__ __forceinline__ void tri_setup(const float* pd, int D, int* ii, float* ff) {
    float dim = (float)(D - 1);
    float hi = dim - 1e-4f;
    #pragma unroll
    for (int c = 0; c < 3; ++c) {
        float t = (pd[c] + 1.f) * 0.5f * dim;
        t = fminf(fmaxf(t, 0.f), hi);
        float fl = floorf(t);
        ii[c] = (int)fl;
        ff[c] = t - fl;
    }
}

__device__ __forceinline__ float tri_gather1(const float* __restrict__ g, int D,
                                             int ix, int iy, int iz,
                                             float fx, float fy, float fz) {
    size_t sx = (size_t)D * D;
    int sy = D;
    const float* b = g + (size_t)ix * sx + (size_t)iy * sy + iz;
    float v000 = __ldg(b),            v001 = __ldg(b + 1);
    float v010 = __ldg(b + sy),       v011 = __ldg(b + sy + 1);
    float v100 = __ldg(b + sx),       v101 = __ldg(b + sx + 1);
    float v110 = __ldg(b + sx + sy),  v111 = __ldg(b + sx + sy + 1);
    float c00 = v000 + (v001 - v000) * fz;
    float c01 = v010 + (v011 - v010) * fz;
    float c10 = v100 + (v101 - v100) * fz;
    float c11 = v110 + (v111 - v110) * fz;
    float c0 = c00 + (c01 - c00) * fy;
    float c1 = c10 + (c11 - c10) * fy;
    return c0 + (c1 - c0) * fx;
}

__device__ __forceinline__ float4 lerp4(float4 a, float4 b, float t) {
    return make_float4(a.x + (b.x - a.x) * t, a.y + (b.y - a.y) * t,
                       a.z + (b.z - a.z) * t, a.w + (b.w - a.w) * t);
}

// ---------------- register-tiled f32x2 GEMM with TMA-bulk weight staging ------
// 64 points x OUT cols; 256 threads: ci = tid&15 (CP cols), pi = tid>>4 (4 pts)
template <int OUT, int ACT>
__device__ __forceinline__ void mlp_layer(
    const float* __restrict__ W, const float* __restrict__ bias,
    const float* __restrict__ xs, int xp, int INA, int INP,
    float* __restrict__ ys, int yp,
    float* __restrict__ ws, uint32_t mb0, uint32_t mb1,
    int& ph0, int& ph1, int tid) {
    constexpr int CP = OUT / 16;
    constexpr int NP = CP / 2;
    const int ci = tid & 15;
    const int pi = tid >> 4;
    unsigned long long acc[4][NP];
    #pragma unroll
    for (int r = 0; r < 4; ++r)
        #pragma unroll
        for (int j = 0; j < NP; ++j) acc[r][j] = 0ull;

    const int ntiles = INP / KT;

    auto issue = [&](int t, int buf) {
        if (tid == 0) {
            int rows = INA - t * KT; if (rows > KT) rows = KT;
            uint32_t bytes = (uint32_t)rows * OUT * 4u;
            uint32_t mb = buf ? mb1 : mb0;
            mbar_expect(mb, bytes);
            bulk_g2s(smem_u32(ws + buf * (KT * 128)), W + (size_t)t * KT * OUT,
                     bytes, mb);
        }
    };

    issue(0, 0);
    for (int t = 0; t < ntiles; ++t) {
        const int buf = t & 1;
        if (buf == 0) { mbar_wait(mb0, (uint32_t)ph0); ph0 ^= 1; }
        else          { mbar_wait(mb1, (uint32_t)ph1); ph1 ^= 1; }
        __syncthreads();                       // all threads past previous tile
        if (t + 1 < ntiles) issue(t + 1, buf ^ 1);

        const float* xb = xs + (size_t)(pi * 4) * xp + t * KT;
        const float* wb = ws + buf * (KT * 128);
        #pragma unroll
        for (int k4 = 0; k4 < KT; k4 += 4) {
            float4 xv[4];
            #pragma unroll
            for (int r = 0; r < 4; ++r)
                xv[r] = *reinterpret_cast<const float4*>(xb + r * xp + k4);
            #pragma unroll
            for (int kk = 0; kk < 4; ++kk) {
                unsigned long long xx[4];
                #pragma unroll
                for (int r = 0; r < 4; ++r) {
                    float xsv = (kk == 0) ? xv[r].x : (kk == 1) ? xv[r].y
                              : (kk == 2) ? xv[r].z : xv[r].w;
                    xx[r] = dup2(xsv);
                }
                const ulonglong2* wr = reinterpret_cast<const ulonglong2*>(
                    wb + (k4 + kk) * OUT + ci * CP);
                #pragma unroll
                for (int q = 0; q < NP / 2; ++q) {
                    ulonglong2 w2 = wr[q];
                    #pragma unroll
                    for (int r = 0; r < 4; ++r) {
                        ffma2(acc[r][2 * q],     xx[r], w2.x);
                        ffma2(acc[r][2 * q + 1], xx[r], w2.y);
                    }
                }
            }
        }
    }

    #pragma unroll
    for (int j = 0; j < NP; ++j) {
        float b0 = __ldg(bias + ci * CP + 2 * j);
        float b1 = __ldg(bias + ci * CP + 2 * j + 1);
        #pragma unroll
        for (int r = 0; r < 4; ++r) {
            float2 p = *reinterpret_cast<float2*>(&acc[r][j]);
            float v0 = p.x + b0, v1 = p.y + b1;
            if (ACT) { v0 = fmaxf(v0, 0.f); v1 = fmaxf(v1, 0.f); }
            const int row = pi * 4 + r;
            ys[(size_t)row * yp + ci * CP + 2 * j]     = v0;
            ys[(size_t)row * yp + ci * CP + 2 * j + 1] = v1;
        }
    }
}

// ---------------- fused main kernel: one block = one ray ----------------
__global__ void __launch_bounds__(NTHREADS, 2)
voxelmlp_main(const float* __restrict__ ray_pts,
              const float* __restrict__ viewdirs,
              const float* __restrict__ density,
              const float* __restrict__ dt_w0, const float* __restrict__ dt_b0,
              const float* __restrict__ dt_w1, const float* __restrict__ dt_b1,
              const float* __restrict__ dt_wo, const float* __restrict__ dt_bo,
              const float* __restrict__ fn_w0, const float* __restrict__ fn_b0,
              const float* __restrict__ dec_wf, const float* __restrict__ dec_bf,
              const float* __restrict__ dec_w0, const float* __restrict__ dec_b0,
              const float* __restrict__ dec_w1, const float* __restrict__ dec_b1,
              float* __restrict__ out) {
    extern __shared__ float sm[];
    float* A     = sm + OFF_A;
    float* Bb    = sm + OFF_B;
    float* WS    = sm + OFF_WS;
    float* W3    = sm + OFF_W3;
    float* W3B   = sm + OFF_W3B;
    float* PD    = sm + OFF_PD;
    float* ALP   = sm + OFF_ALP;
    float* WGT   = sm + OFF_WGT;
    float* RGB   = sm + OFF_RGB;
    float* VE    = sm + OFF_VE;
    float* ALAST = sm + OFF_ALAST;
    int*   TI    = reinterpret_cast<int*>(sm + OFF_TI);
    float* TFR   = sm + OFF_TFR;
    const uint32_t mb0 = smem_u32(sm + OFF_MB);
    const uint32_t mb1 = mb0 + 8;

    const int tid   = threadIdx.x;
    const int ray   = blockIdx.x;
    const int gbase = ray * PPR_C;
    int ph0 = 0, ph1 = 0;

    // ---- init: zero weight buffers (stale-NaN guard), init mbarriers ----
    for (int i = tid; i < 2 * KT * 128; i += NTHREADS) WS[i] = 0.f;
    if (tid == 0) { mbar_init(mb0, 1); mbar_init(mb1, 1); }
    asm volatile("fence.proxy.async.shared::cta;" ::: "memory");

    // stage small weights to smem
    for (int i = tid; i < 128 * 3; i += NTHREADS) W3[i] = __ldg(dt_wo + i);
    if (tid < 3) W3[384 + tid] = __ldg(dt_bo + tid);
    for (int i = tid; i < 64 * 3; i += NTHREADS) W3B[i] = __ldg(dec_w1 + i);
    if (tid < 3) W3B[192 + tid] = __ldg(dec_b1 + tid);

    // ---- phase 0: deform input X = [pts_emb(27), tf(60)], pad -> 96 ----
    if (tid < 64) {
        const int p = tid;
        float* row = A + p * AP;
        #pragma unroll
        for (int d = 0; d < 3; ++d) {
            float v = ray_pts[(size_t)(gbase + p) * 3 + d];
            row[d] = v;
            float s, c;
            __sincosf(v, &s, &c);
            row[3 + d * 4]  = s;
            row[15 + d * 4] = c;
            #pragma unroll
            for (int k = 1; k < 4; ++k) {
                float s2 = 2.f * s * c;
                float c2 = fmaf(-2.f * s, s, 1.f);
                s = s2; c = c2;
                row[3 + d * 4 + k]  = s;
                row[15 + d * 4 + k] = c;
            }
        }
    }
    if (tid >= 64 && tid < 67) {  // view embedding
        const int d = tid - 64;
        float v = viewdirs[(size_t)ray * 3 + d];
        VE[d] = v;
        float s, c;
        __sincosf(v, &s, &c);
        VE[3 + d * 3]  = s;
        VE[12 + d * 3] = c;
        #pragma unroll
        for (int k = 1; k < 3; ++k) {
            float s2 = 2.f * s * c;
            float c2 = fmaf(-2.f * s, s, 1.f);
            s = s2; c = c2;
            VE[3 + d * 3 + k]  = s;
            VE[12 + d * 3 + k] = c;
        }
    }
    for (int i = tid; i < 64 * 60; i += NTHREADS) {
        int p = i & 63, j = i >> 6;
        A[p * AP + 27 + j] = g_tf[j];
    }
    for (int i = tid; i < 64 * 9; i += NTHREADS) {
        int p = i & 63, j = i >> 6;
        A[p * AP + 87 + j] = 0.f;
    }
    __syncthreads();

    // ---- deformation net ----
    mlp_layer<128, 1>(dt_w0, dt_b0, A, AP, 87, 96, Bb, BP, WS, mb0, mb1, ph0, ph1, tid);
    __syncthreads();
    mlp_layer<128, 1>(dt_w1, dt_b1, Bb, BP, 128, 128, A, AP, WS, mb0, mb1, ph0, ph1, tid);
    __syncthreads();

    {   // dx = H @ dt_wo + dt_bo (quad-parallel, weights from smem)
        const int p  = tid >> 2;
        const int l4 = tid & 3;
        float d0 = 0.f, d1 = 0.f, d2 = 0.f;
        const float* row = A + p * AP;
        #pragma unroll 8
        for (int k = l4; k < 128; k += 4) {
            float h = row[k];
            d0 = fmaf(h, W3[k * 3 + 0], d0);
            d1 = fmaf(h, W3[k * 3 + 1], d1);
            d2 = fmaf(h, W3[k * 3 + 2], d2);
        }
        d0 += __shfl_xor_sync(0xffffffffu, d0, 1);
        d0 += __shfl_xor_sync(0xffffffffu, d0, 2);
        d1 += __shfl_xor_sync(0xffffffffu, d1, 1);
        d1 += __shfl_xor_sync(0xffffffffu, d1, 2);
        d2 += __shfl_xor_sync(0xffffffffu, d2, 1);
        d2 += __shfl_xor_sync(0xffffffffu, d2, 2);
        if (l4 == 0) {
            PD[p * 3 + 0] = ray_pts[(size_t)(gbase + p) * 3 + 0] + d0 + W3[384];
            PD[p * 3 + 1] = ray_pts[(size_t)(gbase + p) * 3 + 1] + d1 + W3[385];
            PD[p * 3 + 2] = ray_pts[(size_t)(gbase + p) * 3 + 2] + d2 + W3[386];
        }
    }
    __syncthreads();

    // ---- density -> alpha ----
    if (tid < 64) {
        const int p = tid;
        int ii[3]; float ff[3];
        tri_setup(PD + p * 3, GRID_C, ii, ff);
        float dens = tri_gather1(density, GRID_C, ii[0], ii[1], ii[2],
                                 ff[0], ff[1], ff[2]);
        float x = dens + ACT_SHIFT_C;
        float sp = (x > 20.f) ? x : log1pf(__expf(x));
        ALP[p] = 1.f - __expf(-sp * 0.5f);
    }
    __syncthreads();
    if (tid == 0) {  // per-ray exclusive cumprod
        float T = 1.f;
        for (int i = 0; i < PPR_C; ++i) {
            float a = ALP[i];
            WGT[i] = a * T;
            T *= (1.f - a);
        }
        ALAST[0] = T;
    }

    // ---- 3-scale feature trilerp (transposed grids, float4 gathers) ----
    #pragma unroll 1
    for (int s = 0; s < 3; ++s) {
        const int D = GRID_C >> s;
        if (tid < 64) {
            int ii[3]; float ff[3];
            tri_setup(PD + tid * 3, D, ii, ff);
            TI[tid * 3 + 0] = ii[0]; TI[tid * 3 + 1] = ii[1]; TI[tid * 3 + 2] = ii[2];
            TFR[tid * 3 + 0] = ff[0]; TFR[tid * 3 + 1] = ff[1]; TFR[tid * 3 + 2] = ff[2];
        }
        __syncthreads();
        const float* gp = (s == 0) ? (const float*)g_feat_t
                        : (s == 1) ? (const float*)g_pool2t
                                   : (const float*)g_pool4t;
        {
            const int p = tid >> 2, q = tid & 3;
            if (q < 3) {
                int ix = TI[p * 3 + 0], iy = TI[p * 3 + 1], iz = TI[p * 3 + 2];
                float fx = TFR[p * 3 + 0], fy = TFR[p * 3 + 1], fz = TFR[p * 3 + 2];
                const size_t sy = (size_t)D * VD_C;
                const size_t sx = (size_t)D * sy;
                const float* b = gp + (size_t)ix * sx + (size_t)iy * sy
                               + (size_t)iz * VD_C + q * 4;
                float4 v000 = __ldg((const float4*)(b));
                float4 v001 = __ldg((const float4*)(b + VD_C));
                float4 v010 = __ldg((const float4*)(b + sy));
                float4 v011 = __ldg((const float4*)(b + sy + VD_C));
                float4 v100 = __ldg((const float4*)(b + sx));
                float4 v101 = __ldg((const float4*)(b + sx + VD_C));
                float4 v110 = __ldg((const float4*)(b + sx + sy));
                float4 v111 = __ldg((const float4*)(b + sx + sy + VD_C));
                float4 c00 = lerp4(v000, v001, fz);
                float4 c01 = lerp4(v010, v011, fz);
                float4 c10 = lerp4(v100, v101, fz);
                float4 c11 = lerp4(v110, v111, fz);
                float4 c0 = lerp4(c00, c01, fy);
                float4 c1 = lerp4(c10, c11, fy);
                float4 r  = lerp4(c0, c1, fx);
                *reinterpret_cast<float4*>(A + p * AP + s * 12 + q * 4) = r;
            }
        }
        __syncthreads();
    }

    // ---- featurenet input: sin_emb(feat,2)(180) + sin_emb(pts_d,4)(27) ----
    for (int i = tid; i < 64 * 36; i += NTHREADS) {
        int p = i & 63, d = i >> 6;
        float* row = A + p * AP;
        float f = row[d];
        float s1, c1;
        __sincosf(f, &s1, &c1);
        float s2 = 2.f * s1 * c1;
        float c2 = fmaf(-2.f * s1, s1, 1.f);
        row[36 + 2 * d]  = s1;  row[37 + 2 * d]  = s2;
        row[108 + 2 * d] = c1;  row[109 + 2 * d] = c2;
    }
    if (tid < 64) {
        const int p = tid;
        float* row = A + p * AP;
        #pragma unroll
        for (int d = 0; d < 3; ++d) {
            float v = PD[p * 3 + d];
            row[180 + d] = v;
            float s, c;
            __sincosf(v, &s, &c);
            row[183 + d * 4] = s;
            row[195 + d * 4] = c;
            #pragma unroll
            for (int k = 1; k < 4; ++k) {
                float s2 = 2.f * s * c;
                float c2 = fmaf(-2.f * s, s, 1.f);
                s = s2; c = c2;
                row[183 + d * 4 + k] = s;
                row[195 + d * 4 + k] = c;
            }
        }
        row[207] = 0.f;
    }
    __syncthreads();

    // ---- featurenet + decoder ----
    mlp_layer<128, 1>(fn_w0, fn_b0, A, AP, 207, 208, Bb, BP, WS, mb0, mb1, ph0, ph1, tid);
    __syncthreads();
    mlp_layer<128, 0>(dec_wf, dec_bf, Bb, BP, 128, 128, A, AP, WS, mb0, mb1, ph0, ph1, tid);
    __syncthreads();
    if (tid < 64) {  // append vemb; pad to 160
        float* row = A + tid * AP;
        #pragma unroll
        for (int j = 0; j < 21; ++j) row[128 + j] = VE[j];
        #pragma unroll
        for (int j = 149; j < 160; ++j) row[j] = 0.f;
    }
    __syncthreads();
    mlp_layer<64, 1>(dec_w0, dec_b0, A, AP, 149, 160, Bb, BP, WS, mb0, mb1, ph0, ph1, tid);
    __syncthreads();

    {   // final 64->3 + sigmoid (quad-parallel, weights from smem)
        const int p  = tid >> 2;
        const int l4 = tid & 3;
        float r0 = 0.f, r1 = 0.f, r2 = 0.f;
        const float* row = Bb + p * BP;
        #pragma unroll 4
        for (int k = l4; k < 64; k += 4) {
            float h = row[k];
            r0 = fmaf(h, W3B[k * 3 + 0], r0);
            r1 = fmaf(h, W3B[k * 3 + 1], r1);
            r2 = fmaf(h, W3B[k * 3 + 2], r2);
        }
        r0 += __shfl_xor_sync(0xffffffffu, r0, 1);
        r0 += __shfl_xor_sync(0xffffffffu, r0, 2);
        r1 += __shfl_xor_sync(0xffffffffu, r1, 1);
        r1 += __shfl_xor_sync(0xffffffffu, r1, 2);
        r2 += __shfl_xor_sync(0xffffffffu, r2, 1);
        r2 += __shfl_xor_sync(0xffffffffu, r2, 2);
        if (l4 == 0) {
            r0 += W3B[192]; r1 += W3B[193]; r2 += W3B[194];
            RGB[p * 3 + 0] = 1.f / (1.f + __expf(-r0));
            RGB[p * 3 + 1] = 1.f / (1.f + __expf(-r1));
            RGB[p * 3 + 2] = 1.f / (1.f + __expf(-r2));
        }
    }
    __syncthreads();

    if (tid < 3) {  // composite with white background
        float s = ALAST[0];
        for (int p = 0; p < PPR_C; ++p) s = fmaf(WGT[p], RGB[p * 3 + tid], s);
        out[(size_t)ray * 3 + tid] = s;
    }
}

// ---------------- launch ----------------
extern "C" void kernel_launch(void* const* d_in, const int* in_sizes, int n_in,
                              void* d_out, int out_size) {
    (void)in_sizes; (void)n_in; (void)out_size;
    const float* ray_pts    = (const float*)d_in[0];
    const float* viewdirs   = (const float*)d_in[1];
    const float* frame_time = (const float*)d_in[2];
    const float* feature    = (const float*)d_in[3];
    const float* density    = (const float*)d_in[4];
    const float* tn_w0 = (const float*)d_in[5];
    const float* tn_b0 = (const float*)d_in[6];
    const float* tn_w1 = (const float*)d_in[7];
    const float* tn_b1 = (const float*)d_in[8];
    const float* dt_w0 = (const float*)d_in[9];
    const float* dt_b0 = (const float*)d_in[10];
    const float* dt_w1 = (const float*)d_in[11];
    const float* dt_b1 = (const float*)d_in[12];
    const float* dt_wo = (const float*)d_in[13];
    const float* dt_bo = (const float*)d_in[14];
    const float* fn_w0 = (const float*)d_in[15];
    const float* fn_b0 = (const float*)d_in[16];
    const float* dec_wf = (const float*)d_in[17];
    const float* dec_bf = (const float*)d_in[18];
    const float* dec_w0 = (const float*)d_in[19];
    const float* dec_b0 = (const float*)d_in[20];
    const float* dec_w1 = (const float*)d_in[21];
    const float* dec_b1 = (const float*)d_in[22];
    float* out = (float*)d_out;

    cudaFuncSetAttribute(voxelmlp_main, cudaFuncAttributeMaxDynamicSharedMemorySize,
                         SMEM_BYTES);

    {
        const int V = GRID_C * GRID_C * GRID_C;
        transpose_feat<<<(V + 255) / 256, 256>>>(feature);
    }
    pool2t_kernel<<<(64 * 64 * 64 + 255) / 256, 256>>>();
    pool4t_kernel<<<(32 * 32 * 32 + 255) / 256, 256>>>();
    timenet_kernel<<<1, 128>>>(frame_time, tn_w0, tn_b0, tn_w1, tn_b1);

    voxelmlp_main<<<N_RAYS_C, NTHREADS, SMEM_BYTES>>>(
        ray_pts, viewdirs, density,
        dt_w0, dt_b0, dt_w1, dt_b1, dt_wo, dt_bo,
        fn_w0, fn_b0, dec_wf, dec_bf,
        dec_w0, dec_b0, dec_w1, dec_b1,
        out);
}